// round 1
// baseline (speedup 1.0000x reference)
#include <cuda_runtime.h>
#include <math.h>

#define N_OP 20000
#define N_M  500
#define NE   200000
#define DD   256
#define HH   8

#define LD_OP 1792   // [q | ka0 | ka1 | ka2 | va0 | va1 | va2]
#define LD_M  768    // [q | ka3 | va3]

// ---------------- scratch (static device allocations only) ----------------
__device__ float g_x0[N_OP * DD];                    // x_op + temporal scatter
__device__ float g_proj_op[(size_t)N_OP * LD_OP];    // stacked projections (ops)
__device__ float g_proj_m[N_M * LD_M];               // stacked projections (machines)
__device__ float g_wop[LD_OP * DD];                  // stacked weights (ops)
__device__ float g_bop[LD_OP];
__device__ float g_wm[LD_M * DD];
__device__ float g_bm[LD_M];
__device__ float g_expa[4 * (size_t)NE * HH];
__device__ float g_denom_op[3 * N_OP * HH];          // edge types 0,1,3 -> slots 0,1,2
__device__ float g_denom_m[N_M * HH];
__device__ float g_out_op[N_OP * DD];
__device__ float g_out_m[N_M * DD];

// ---------------- init ----------------
__global__ void k_init(const float* __restrict__ x_op) {
    int i = blockIdx.x * blockDim.x + threadIdx.x;
    if (i < N_OP * DD / 4) {
        ((float4*)g_x0)[i] = ((const float4*)x_op)[i];
        ((float4*)g_out_op)[i] = make_float4(0.f, 0.f, 0.f, 0.f);
    }
}

__global__ void k_zero2() {
    int i = blockIdx.x * blockDim.x + threadIdx.x;
    if (i < 3 * N_OP * HH) g_denom_op[i] = 0.f;
    if (i < N_M * DD) g_out_m[i] = 0.f;
    if (i < N_M * HH) g_denom_m[i] = 0.f;
}

// ---------------- weight stacking: fold a_rel/m_rel into Wk/Wv ----------------
// blockIdx.x = row in [0, LD_OP + LD_M); 256 threads = input dim
__global__ void k_wstack(const float* __restrict__ Wk, const float* __restrict__ bk,
                         const float* __restrict__ Wq, const float* __restrict__ bq,
                         const float* __restrict__ Wv, const float* __restrict__ bv,
                         const float* __restrict__ a_rel, const float* __restrict__ m_rel) {
    int row = blockIdx.x;
    int in = threadIdx.x;
    float* wdst; float* bdst; int t;
    if (row < LD_OP) { wdst = g_wop; bdst = g_bop; t = 0; }
    else             { row -= LD_OP; wdst = g_wm; bdst = g_bm; t = 1; }
    int seg = row >> 8, o = row & 255;
    if (seg == 0) {  // plain q copy
        wdst[row * DD + in] = Wq[t * 65536 + o * DD + in];
        if (in == 0) bdst[row] = bq[t * DD + o];
        return;
    }
    const float* rel; const float* Wb; const float* bb; int e;
    if (t == 0) {
        if (seg <= 3) { e = seg - 1; rel = a_rel; Wb = Wk; bb = bk; }
        else          { e = seg - 4; rel = m_rel; Wb = Wv; bb = bv; }
    } else {
        e = 3;
        if (seg == 1) { rel = a_rel; Wb = Wk; bb = bk; }
        else          { rel = m_rel; Wb = Wv; bb = bv; }
    }
    int h = o >> 5, f = o & 31;
    const float* rp = rel + ((e * 8 + h) * 32) * 32 + f;       // stride 32 over d
    const float* W = Wb + t * 65536 + (h * 32) * DD;
    float acc = 0.f;
#pragma unroll 8
    for (int d = 0; d < 32; d++) acc += rp[d * 32] * W[d * DD + in];
    wdst[row * DD + in] = acc;
    if (in == 0) {
        float bacc = 0.f;
        const float* b = bb + t * DD + h * 32;
        for (int d = 0; d < 32; d++) bacc += rp[d * 32] * b[d];
        bdst[row] = bacc;
    }
}

// ---------------- temporal encoding + LayerNorm + scatter-add ----------------
__global__ void k_temporal(const float* __restrict__ dtp, const int* __restrict__ ei,
                           const float* __restrict__ Wt, const float* __restrict__ bt,
                           const float* __restrict__ lng, const float* __restrict__ lnb) {
    __shared__ float sW[16 * DD];   // transposed: [c][row] -> conflict-free reads
    __shared__ float sbt[DD], sg[DD], sb[DD];
    for (int i = threadIdx.x; i < 16 * DD; i += blockDim.x) {
        int row = i >> 4, c = i & 15;
        sW[c * DD + row] = Wt[i];
    }
    for (int i = threadIdx.x; i < DD; i += blockDim.x) { sbt[i] = bt[i]; sg[i] = lng[i]; sb[i] = lnb[i]; }
    __syncthreads();
    int gw = (blockIdx.x * blockDim.x + threadIdx.x) >> 5;
    int lane = threadIdx.x & 31;
    int nw = (gridDim.x * blockDim.x) >> 5;
    for (int e = gw; e < NE; e += nw) {
        float dt = dtp[e];
        float temb[16];
#pragma unroll
        for (int j = 0; j < 8; j++) {
            // freq_j = 1000^(-j/8) = 2^(-log2(1000)/8 * j)
            float s, c;
            sincosf(dt * exp2f(-1.2457230355827609f * (float)j), &s, &c);
            temb[2 * j] = s; temb[2 * j + 1] = c;
        }
        float pt[8], s1 = 0.f, s2 = 0.f;
#pragma unroll
        for (int r = 0; r < 8; r++) {
            int row = lane + 32 * r;
            float acc = sbt[row];
#pragma unroll
            for (int c = 0; c < 16; c++) acc += sW[c * DD + row] * temb[c];
            pt[r] = acc; s1 += acc; s2 += acc * acc;
        }
#pragma unroll
        for (int o = 16; o; o >>= 1) {
            s1 += __shfl_xor_sync(0xffffffffu, s1, o);
            s2 += __shfl_xor_sync(0xffffffffu, s2, o);
        }
        float mu = s1 * (1.f / 256.f);
        float var = fmaf(-mu, mu, s2 * (1.f / 256.f));
        float rs = rsqrtf(var + 1e-5f);
        int src = ei[e];                     // row 0 = source op
        float* dst = g_x0 + (size_t)src * DD;
#pragma unroll
        for (int r = 0; r < 8; r++) {
            int row = lane + 32 * r;
            atomicAdd(dst + row, (pt[r] - mu) * rs * sg[row] + sb[row]);
        }
    }
}

// ---------------- generic fp32 GEMM: C = A[M,256] @ W[N,256]^T + bias (+gated skip) --------
__global__ void k_gemm(const float* __restrict__ A, const float* __restrict__ W,
                       const float* __restrict__ bias, float* __restrict__ C,
                       int M, int N, int lda, int ldc,
                       const float* __restrict__ skipX, const float* __restrict__ skipP,
                       int skipIdx) {
    const int K = 256;
    __shared__ float As[16 * 65];
    __shared__ float Ws[16 * 65];
    int tid = threadIdx.x;
    int tx = tid & 15, ty = tid >> 4;
    int m0 = blockIdx.y * 64, n0 = blockIdx.x * 64;
    float acc[4][4] = {};
    int lr = tid >> 2;           // 0..63
    int lc = (tid & 3) * 4;      // 0,4,8,12
    for (int k0 = 0; k0 < K; k0 += 16) {
        int gm = m0 + lr;
        float4 av = make_float4(0.f, 0.f, 0.f, 0.f);
        if (gm < M) av = *(const float4*)&A[(size_t)gm * lda + k0 + lc];
        As[(lc + 0) * 65 + lr] = av.x; As[(lc + 1) * 65 + lr] = av.y;
        As[(lc + 2) * 65 + lr] = av.z; As[(lc + 3) * 65 + lr] = av.w;
        float4 wv = *(const float4*)&W[(size_t)(n0 + lr) * K + k0 + lc];
        Ws[(lc + 0) * 65 + lr] = wv.x; Ws[(lc + 1) * 65 + lr] = wv.y;
        Ws[(lc + 2) * 65 + lr] = wv.z; Ws[(lc + 3) * 65 + lr] = wv.w;
        __syncthreads();
#pragma unroll
        for (int kk = 0; kk < 16; kk++) {
            float a0 = As[kk * 65 + ty * 4 + 0], a1 = As[kk * 65 + ty * 4 + 1];
            float a2 = As[kk * 65 + ty * 4 + 2], a3 = As[kk * 65 + ty * 4 + 3];
            float b0 = Ws[kk * 65 + tx * 4 + 0], b1 = Ws[kk * 65 + tx * 4 + 1];
            float b2 = Ws[kk * 65 + tx * 4 + 2], b3 = Ws[kk * 65 + tx * 4 + 3];
            acc[0][0] += a0 * b0; acc[0][1] += a0 * b1; acc[0][2] += a0 * b2; acc[0][3] += a0 * b3;
            acc[1][0] += a1 * b0; acc[1][1] += a1 * b1; acc[1][2] += a1 * b2; acc[1][3] += a1 * b3;
            acc[2][0] += a2 * b0; acc[2][1] += a2 * b1; acc[2][2] += a2 * b2; acc[2][3] += a2 * b3;
            acc[3][0] += a3 * b0; acc[3][1] += a3 * b1; acc[3][2] += a3 * b2; acc[3][3] += a3 * b3;
        }
        __syncthreads();
    }
    bool hs = (skipX != nullptr);
    float sa = 0.f, sbv = 0.f;
    if (hs) { float s = skipP[skipIdx]; sa = 1.f / (1.f + __expf(-s)); sbv = 1.f - sa; }
#pragma unroll
    for (int i = 0; i < 4; i++) {
        int m = m0 + ty * 4 + i;
        if (m >= M) break;
#pragma unroll
        for (int j = 0; j < 4; j++) {
            int n = n0 + tx * 4 + j;
            float v = acc[i][j] + bias[n];
            if (hs) v = sa * v + sbv * skipX[(size_t)m * DD + n];
            C[(size_t)m * ldc + n] = v;
        }
    }
}

// ---------------- edge pass A: alpha -> expa, denom ----------------
__global__ void k_edge_alpha(const int* __restrict__ ei, int E,
                             const float* __restrict__ qb, int qld,
                             const float* __restrict__ kb, int kld,
                             const float* __restrict__ prel,
                             float* __restrict__ expa, float* __restrict__ denom) {
    int w = (blockIdx.x * blockDim.x + threadIdx.x) >> 5;
    if (w >= E) return;
    int lane = threadIdx.x & 31;
    int src = ei[w], dst = ei[E + w];
    const float4* q = (const float4*)(qb + (size_t)dst * qld);
    const float4* k = (const float4*)(kb + (size_t)src * kld);
    float4 q0 = q[lane * 2], q1 = q[lane * 2 + 1];
    float4 k0 = k[lane * 2], k1 = k[lane * 2 + 1];
    float p = q0.x * k0.x + q0.y * k0.y + q0.z * k0.z + q0.w * k0.w
            + q1.x * k1.x + q1.y * k1.y + q1.z * k1.z + q1.w * k1.w;
    p += __shfl_xor_sync(0xffffffffu, p, 1);
    p += __shfl_xor_sync(0xffffffffu, p, 2);
    float v = __shfl_sync(0xffffffffu, p, (lane * 4) & 31);   // lane h<8 gets head h
    if (lane < 8) {
        float ex = __expf(v * prel[lane] * 0.17677669529663687f);  // 1/sqrt(32)
        expa[(size_t)w * 8 + lane] = ex;
        atomicAdd(&denom[(size_t)dst * 8 + lane], ex);
    }
}

// ---------------- edge pass B: scatter v * softmax-weight ----------------
__global__ void k_edge_scatter(const int* __restrict__ ei, int E,
                               const float* __restrict__ vb, int vld,
                               const float* __restrict__ expa, const float* __restrict__ denom,
                               float* __restrict__ out) {
    int w = (blockIdx.x * blockDim.x + threadIdx.x) >> 5;
    if (w >= E) return;
    int lane = threadIdx.x & 31;
    int src = ei[w], dst = ei[E + w];
    float wgt = 0.f;
    if (lane < 8) wgt = expa[(size_t)w * 8 + lane] / denom[(size_t)dst * 8 + lane];
    float wh = __shfl_sync(0xffffffffu, wgt, lane >> 2);      // head = (lane*8)/32
    const float4* v = (const float4*)(vb + (size_t)src * vld);
    float4 v0 = v[lane * 2], v1 = v[lane * 2 + 1];
    float* o = out + (size_t)dst * DD + lane * 8;
    atomicAdd(o + 0, v0.x * wh); atomicAdd(o + 1, v0.y * wh);
    atomicAdd(o + 2, v0.z * wh); atomicAdd(o + 3, v0.w * wh);
    atomicAdd(o + 4, v1.x * wh); atomicAdd(o + 5, v1.y * wh);
    atomicAdd(o + 6, v1.z * wh); atomicAdd(o + 7, v1.w * wh);
}

// ---------------- exact GELU (in-place) ----------------
__global__ void k_gelu() {
    int i = blockIdx.x * blockDim.x + threadIdx.x;
    if (i < N_OP * DD) {
        float x = g_out_op[i];
        g_out_op[i] = 0.5f * x * (1.f + erff(x * 0.70710678118654752f));
    }
    if (i < N_M * DD) {
        float x = g_out_m[i];
        g_out_m[i] = 0.5f * x * (1.f + erff(x * 0.70710678118654752f));
    }
}

// ---------------- launch ----------------
extern "C" void kernel_launch(void* const* d_in, const int* in_sizes, int n_in,
                              void* d_out, int out_size) {
    const float* x_op = (const float*)d_in[0];
    const float* x_m  = (const float*)d_in[1];
    const float* dtp  = (const float*)d_in[2];
    const int* ei_mp  = (const int*)d_in[3];
    const int* ei_pr  = (const int*)d_in[4];
    const int* ei_on  = (const int*)d_in[5];
    const int* ei_ho  = (const int*)d_in[6];
    const float* Wt   = (const float*)d_in[7];
    const float* bt   = (const float*)d_in[8];
    const float* lng  = (const float*)d_in[9];
    const float* lnb  = (const float*)d_in[10];
    const float* Wk   = (const float*)d_in[11];
    const float* bk   = (const float*)d_in[12];
    const float* Wq   = (const float*)d_in[13];
    const float* bq   = (const float*)d_in[14];
    const float* Wv   = (const float*)d_in[15];
    const float* bv   = (const float*)d_in[16];
    const float* Wa   = (const float*)d_in[17];
    const float* ba   = (const float*)d_in[18];
    const float* skip = (const float*)d_in[19];
    const float* a_rel = (const float*)d_in[20];
    const float* m_rel = (const float*)d_in[21];
    const float* p_rel = (const float*)d_in[22];
    float* out = (float*)d_out;

    float *p_x0, *p_proj_op, *p_proj_m, *p_wop, *p_bop, *p_wm, *p_bm;
    float *p_expa, *p_dop, *p_dm, *p_oop, *p_om;
    cudaGetSymbolAddress((void**)&p_x0, g_x0);
    cudaGetSymbolAddress((void**)&p_proj_op, g_proj_op);
    cudaGetSymbolAddress((void**)&p_proj_m, g_proj_m);
    cudaGetSymbolAddress((void**)&p_wop, g_wop);
    cudaGetSymbolAddress((void**)&p_bop, g_bop);
    cudaGetSymbolAddress((void**)&p_wm, g_wm);
    cudaGetSymbolAddress((void**)&p_bm, g_bm);
    cudaGetSymbolAddress((void**)&p_expa, g_expa);
    cudaGetSymbolAddress((void**)&p_dop, g_denom_op);
    cudaGetSymbolAddress((void**)&p_dm, g_denom_m);
    cudaGetSymbolAddress((void**)&p_oop, g_out_op);
    cudaGetSymbolAddress((void**)&p_om, g_out_m);

    int E0 = in_sizes[3] / 2, E1 = in_sizes[4] / 2, E2 = in_sizes[5] / 2, E3 = in_sizes[6] / 2;

    k_init<<<(N_OP * DD / 4 + 255) / 256, 256>>>(x_op);
    k_zero2<<<(3 * N_OP * HH + 255) / 256, 256>>>();
    k_wstack<<<LD_OP + LD_M, 256>>>(Wk, bk, Wq, bq, Wv, bv, a_rel, m_rel);
    k_temporal<<<1024, 256>>>(dtp, ei_mp, Wt, bt, lng, lnb);

    // stacked projections
    k_gemm<<<dim3(LD_OP / 64, (N_OP + 63) / 64), 256>>>(
        p_x0, p_wop, p_bop, p_proj_op, N_OP, LD_OP, DD, LD_OP, nullptr, nullptr, 0);
    k_gemm<<<dim3(LD_M / 64, (N_M + 63) / 64), 256>>>(
        x_m, p_wm, p_bm, p_proj_m, N_M, LD_M, DD, LD_M, nullptr, nullptr, 0);

    // pass A: alpha / exp / denom    (edge types: mp, prec, on, hosts)
    k_edge_alpha<<<(E0 + 7) / 8, 256>>>(ei_mp, E0, p_proj_op, LD_OP, p_proj_op + 256, LD_OP,
                                        p_rel + 0, p_expa, p_dop);
    k_edge_alpha<<<(E1 + 7) / 8, 256>>>(ei_pr, E1, p_proj_op, LD_OP, p_proj_op + 512, LD_OP,
                                        p_rel + 8, p_expa + (size_t)NE * 8, p_dop + N_OP * HH);
    k_edge_alpha<<<(E2 + 7) / 8, 256>>>(ei_on, E2, p_proj_m, LD_M, p_proj_op + 768, LD_OP,
                                        p_rel + 16, p_expa + (size_t)2 * NE * 8, p_dm);
    k_edge_alpha<<<(E3 + 7) / 8, 256>>>(ei_ho, E3, p_proj_op, LD_OP, p_proj_m + 256, LD_M,
                                        p_rel + 24, p_expa + (size_t)3 * NE * 8, p_dop + 2 * N_OP * HH);

    // pass B: weighted scatter
    k_edge_scatter<<<(E0 + 7) / 8, 256>>>(ei_mp, E0, p_proj_op + 1024, LD_OP,
                                          p_expa, p_dop, p_oop);
    k_edge_scatter<<<(E1 + 7) / 8, 256>>>(ei_pr, E1, p_proj_op + 1280, LD_OP,
                                          p_expa + (size_t)NE * 8, p_dop + N_OP * HH, p_oop);
    k_edge_scatter<<<(E2 + 7) / 8, 256>>>(ei_on, E2, p_proj_op + 1536, LD_OP,
                                          p_expa + (size_t)2 * NE * 8, p_dm, p_om);
    k_edge_scatter<<<(E3 + 7) / 8, 256>>>(ei_ho, E3, p_proj_m + 512, LD_M,
                                          p_expa + (size_t)3 * NE * 8, p_dop + 2 * N_OP * HH, p_oop);

    k_gelu<<<(N_OP * DD + 255) / 256, 256>>>();

    // final GEMMs with fused sigmoid-gated skip, writing directly to d_out
    k_gemm<<<dim3(256 / 64, (N_OP + 63) / 64), 256>>>(
        p_oop, Wa, ba, out, N_OP, 256, DD, DD, p_x0, skip, 0);
    k_gemm<<<dim3(256 / 64, (N_M + 63) / 64), 256>>>(
        p_om, Wa + 65536, ba + 256, out + (size_t)N_OP * DD, N_M, 256, DD, DD, x_m, skip, 1);
}

// round 3
// speedup vs baseline: 1.7552x; 1.7552x over previous
#include <cuda_runtime.h>
#include <math.h>

#define N_OP 20000
#define N_M  500
#define NE   200000
#define DD   256
#define HH   8

#define LD_OP 1792   // [q | ka0 | ka1 | ka2 | va0 | va1 | va2]
#define LD_M  768    // [q | ka3 | va3]

// ---------------- scratch ----------------
__device__ float g_x0[N_OP * DD];
__device__ float g_proj_op[(size_t)N_OP * LD_OP];
__device__ float g_proj_m[N_M * LD_M];
__device__ float g_wop[LD_OP * DD];
__device__ float g_bop[LD_OP];
__device__ float g_wm[LD_M * DD];
__device__ float g_bm[LD_M];
__device__ float g_expa[4 * (size_t)NE * HH];
__device__ float g_denom_op[3 * N_OP * HH];
__device__ float g_denom_m[N_M * HH];
__device__ float g_out_op[N_OP * DD];
__device__ float g_out_m[N_M * DD];

__device__ __forceinline__ void red_add_v4(float* p, float4 v) {
    asm volatile("red.global.add.v4.f32 [%0], {%1,%2,%3,%4};"
                 :: "l"(p), "f"(v.x), "f"(v.y), "f"(v.z), "f"(v.w) : "memory");
}

// ---------------- init ----------------
__global__ void k_init(const float* __restrict__ x_op) {
    int i = blockIdx.x * blockDim.x + threadIdx.x;
    if (i < N_OP * DD / 4) {
        ((float4*)g_x0)[i] = ((const float4*)x_op)[i];
        ((float4*)g_out_op)[i] = make_float4(0.f, 0.f, 0.f, 0.f);
    }
}

__global__ void k_zero2() {
    int i = blockIdx.x * blockDim.x + threadIdx.x;
    if (i < 3 * N_OP * HH) g_denom_op[i] = 0.f;
    if (i < N_M * DD) g_out_m[i] = 0.f;
    if (i < N_M * HH) g_denom_m[i] = 0.f;
}

// ---------------- weight stacking ----------------
__global__ void k_wstack(const float* __restrict__ Wk, const float* __restrict__ bk,
                         const float* __restrict__ Wq, const float* __restrict__ bq,
                         const float* __restrict__ Wv, const float* __restrict__ bv,
                         const float* __restrict__ a_rel, const float* __restrict__ m_rel) {
    int row = blockIdx.x;
    int in = threadIdx.x;
    float* wdst; float* bdst; int t;
    if (row < LD_OP) { wdst = g_wop; bdst = g_bop; t = 0; }
    else             { row -= LD_OP; wdst = g_wm; bdst = g_bm; t = 1; }
    int seg = row >> 8, o = row & 255;
    if (seg == 0) {
        wdst[row * DD + in] = Wq[t * 65536 + o * DD + in];
        if (in == 0) bdst[row] = bq[t * DD + o];
        return;
    }
    const float* rel; const float* Wb; const float* bb; int e;
    if (t == 0) {
        if (seg <= 3) { e = seg - 1; rel = a_rel; Wb = Wk; bb = bk; }
        else          { e = seg - 4; rel = m_rel; Wb = Wv; bb = bv; }
    } else {
        e = 3;
        if (seg == 1) { rel = a_rel; Wb = Wk; bb = bk; }
        else          { rel = m_rel; Wb = Wv; bb = bv; }
    }
    int h = o >> 5, f = o & 31;
    const float* rp = rel + ((e * 8 + h) * 32) * 32 + f;
    const float* W = Wb + t * 65536 + (h * 32) * DD;
    float acc = 0.f;
#pragma unroll 8
    for (int d = 0; d < 32; d++) acc += rp[d * 32] * W[d * DD + in];
    wdst[row * DD + in] = acc;
    if (in == 0) {
        float bacc = 0.f;
        const float* b = bb + t * DD + h * 32;
        for (int d = 0; d < 32; d++) bacc += rp[d * 32] * b[d];
        bdst[row] = bacc;
    }
}

// ---------------- temporal encoding + LayerNorm + vector scatter-add ----------------
__global__ void k_temporal(const float* __restrict__ dtp, const int* __restrict__ ei,
                           const float* __restrict__ Wt, const float* __restrict__ bt,
                           const float* __restrict__ lng, const float* __restrict__ lnb) {
    __shared__ float sW[16 * DD];
    __shared__ float sbt[DD], sg[DD], sb[DD];
    __shared__ float stage[8 * 256];
    for (int i = threadIdx.x; i < 16 * DD; i += blockDim.x) {
        int row = i >> 4, c = i & 15;
        sW[c * DD + row] = Wt[i];
    }
    for (int i = threadIdx.x; i < DD; i += blockDim.x) { sbt[i] = bt[i]; sg[i] = lng[i]; sb[i] = lnb[i]; }
    __syncthreads();
    int gw = (blockIdx.x * blockDim.x + threadIdx.x) >> 5;
    int lane = threadIdx.x & 31;
    int nw = (gridDim.x * blockDim.x) >> 5;
    float* sh = stage + (threadIdx.x >> 5) * 256;
    for (int e = gw; e < NE; e += nw) {
        float dt = dtp[e];
        float temb[16];
#pragma unroll
        for (int j = 0; j < 8; j++) {
            float s, c;
            sincosf(dt * exp2f(-1.2457230355827609f * (float)j), &s, &c);
            temb[2 * j] = s; temb[2 * j + 1] = c;
        }
        float pt[8], s1 = 0.f, s2 = 0.f;
#pragma unroll
        for (int r = 0; r < 8; r++) {
            int row = lane + 32 * r;
            float acc = sbt[row];
#pragma unroll
            for (int c = 0; c < 16; c++) acc += sW[c * DD + row] * temb[c];
            pt[r] = acc; s1 += acc; s2 += acc * acc;
        }
#pragma unroll
        for (int o = 16; o; o >>= 1) {
            s1 += __shfl_xor_sync(0xffffffffu, s1, o);
            s2 += __shfl_xor_sync(0xffffffffu, s2, o);
        }
        float mu = s1 * (1.f / 256.f);
        float var = fmaf(-mu, mu, s2 * (1.f / 256.f));
        float rs = rsqrtf(var + 1e-5f);
        // stage normalized values so each lane owns 8 contiguous channels
#pragma unroll
        for (int r = 0; r < 8; r++) {
            int row = lane + 32 * r;
            sh[row] = (pt[r] - mu) * rs * sg[row] + sb[row];
        }
        __syncwarp();
        int src = ei[e];
        float* dst = g_x0 + (size_t)src * DD + lane * 8;
        float4 y0 = *(float4*)&sh[lane * 8];
        float4 y1 = *(float4*)&sh[lane * 8 + 4];
        red_add_v4(dst, y0);
        red_add_v4(dst + 4, y1);
        __syncwarp();
    }
}

// ---------------- fp32 GEMM: C = A[M,256] @ W[N,256]^T + bias ----------------
// 128x128 tile, 8x8 microtile, K-slab 8.  N must be a multiple of 128, K == 256.
__global__ void __launch_bounds__(256, 2)
k_gemm(const float* __restrict__ A, const float* __restrict__ W,
       const float* __restrict__ bias, float* __restrict__ C,
       int M, int lda, int ldc,
       const float* __restrict__ skipX, const float* __restrict__ skipP,
       int skipIdx, int geluA) {
    const int K = 256;
    __shared__ float As[8 * 132];
    __shared__ float Ws[8 * 132];
    int tid = threadIdx.x;
    int tx = tid & 15, ty = tid >> 4;
    int m0 = blockIdx.y * 128, n0 = blockIdx.x * 128;
    int lr = tid >> 1;          // 0..127
    int lc = (tid & 1) * 4;     // 0 or 4
    float acc[8][8] = {};
    for (int k0 = 0; k0 < K; k0 += 8) {
        int gm = m0 + lr;
        float4 av = make_float4(0.f, 0.f, 0.f, 0.f);
        if (gm < M) av = *(const float4*)&A[(size_t)gm * lda + k0 + lc];
        if (geluA) {
            av.x = 0.5f * av.x * (1.f + erff(av.x * 0.70710678118654752f));
            av.y = 0.5f * av.y * (1.f + erff(av.y * 0.70710678118654752f));
            av.z = 0.5f * av.z * (1.f + erff(av.z * 0.70710678118654752f));
            av.w = 0.5f * av.w * (1.f + erff(av.w * 0.70710678118654752f));
        }
        As[(lc + 0) * 132 + lr] = av.x; As[(lc + 1) * 132 + lr] = av.y;
        As[(lc + 2) * 132 + lr] = av.z; As[(lc + 3) * 132 + lr] = av.w;
        float4 wv = *(const float4*)&W[(size_t)(n0 + lr) * K + k0 + lc];
        Ws[(lc + 0) * 132 + lr] = wv.x; Ws[(lc + 1) * 132 + lr] = wv.y;
        Ws[(lc + 2) * 132 + lr] = wv.z; Ws[(lc + 3) * 132 + lr] = wv.w;
        __syncthreads();
#pragma unroll
        for (int kk = 0; kk < 8; kk++) {
            float4 a0 = *(const float4*)&As[kk * 132 + ty * 8];
            float4 a1 = *(const float4*)&As[kk * 132 + ty * 8 + 4];
            float4 b0 = *(const float4*)&Ws[kk * 132 + tx * 8];
            float4 b1 = *(const float4*)&Ws[kk * 132 + tx * 8 + 4];
            float a[8] = {a0.x, a0.y, a0.z, a0.w, a1.x, a1.y, a1.z, a1.w};
            float b[8] = {b0.x, b0.y, b0.z, b0.w, b1.x, b1.y, b1.z, b1.w};
#pragma unroll
            for (int i = 0; i < 8; i++)
#pragma unroll
                for (int j = 0; j < 8; j++) acc[i][j] += a[i] * b[j];
        }
        __syncthreads();
    }
    bool hs = (skipX != nullptr);
    float sa = 0.f, sbv = 0.f;
    if (hs) { float s = skipP[skipIdx]; sa = 1.f / (1.f + __expf(-s)); sbv = 1.f - sa; }
    int nbase = n0 + tx * 8;
    float4 bi0 = *(const float4*)&bias[nbase];
    float4 bi1 = *(const float4*)&bias[nbase + 4];
    float bb[8] = {bi0.x, bi0.y, bi0.z, bi0.w, bi1.x, bi1.y, bi1.z, bi1.w};
#pragma unroll
    for (int i = 0; i < 8; i++) {
        int m = m0 + ty * 8 + i;
        if (m >= M) break;
        float v[8];
#pragma unroll
        for (int j = 0; j < 8; j++) {
            v[j] = acc[i][j] + bb[j];
            if (hs) v[j] = sa * v[j] + sbv * skipX[(size_t)m * DD + nbase + j];
        }
        float* cp = &C[(size_t)m * ldc + nbase];
        *(float4*)cp = make_float4(v[0], v[1], v[2], v[3]);
        *(float4*)(cp + 4) = make_float4(v[4], v[5], v[6], v[7]);
    }
}

// ---------------- edge pass A: alpha -> expa, denom ----------------
__global__ void k_edge_alpha(const int* __restrict__ ei, int E,
                             const float* __restrict__ qb, int qld,
                             const float* __restrict__ kb, int kld,
                             const float* __restrict__ prel,
                             float* __restrict__ expa, float* __restrict__ denom) {
    int w = (blockIdx.x * blockDim.x + threadIdx.x) >> 5;
    if (w >= E) return;
    int lane = threadIdx.x & 31;
    int src = ei[w], dst = ei[E + w];
    const float4* q = (const float4*)(qb + (size_t)dst * qld);
    const float4* k = (const float4*)(kb + (size_t)src * kld);
    float4 q0 = q[lane * 2], q1 = q[lane * 2 + 1];
    float4 k0 = k[lane * 2], k1 = k[lane * 2 + 1];
    float p = q0.x * k0.x + q0.y * k0.y + q0.z * k0.z + q0.w * k0.w
            + q1.x * k1.x + q1.y * k1.y + q1.z * k1.z + q1.w * k1.w;
    p += __shfl_xor_sync(0xffffffffu, p, 1);
    p += __shfl_xor_sync(0xffffffffu, p, 2);
    float v = __shfl_sync(0xffffffffu, p, (lane * 4) & 31);
    if (lane < 8) {
        float ex = __expf(v * prel[lane] * 0.17677669529663687f);
        expa[(size_t)w * 8 + lane] = ex;
        atomicAdd(&denom[(size_t)dst * 8 + lane], ex);
    }
}

// ---------------- edge pass B: scatter v * softmax-weight (vector REDs) ----------------
__global__ void k_edge_scatter(const int* __restrict__ ei, int E,
                               const float* __restrict__ vb, int vld,
                               const float* __restrict__ expa, const float* __restrict__ denom,
                               float* __restrict__ out) {
    int w = (blockIdx.x * blockDim.x + threadIdx.x) >> 5;
    if (w >= E) return;
    int lane = threadIdx.x & 31;
    int src = ei[w], dst = ei[E + w];
    float wgt = 0.f;
    if (lane < 8) wgt = expa[(size_t)w * 8 + lane] / denom[(size_t)dst * 8 + lane];
    float wh = __shfl_sync(0xffffffffu, wgt, lane >> 2);
    const float4* v = (const float4*)(vb + (size_t)src * vld);
    float4 v0 = v[lane * 2], v1 = v[lane * 2 + 1];
    float* o = out + (size_t)dst * DD + lane * 8;
    red_add_v4(o, make_float4(v0.x * wh, v0.y * wh, v0.z * wh, v0.w * wh));
    red_add_v4(o + 4, make_float4(v1.x * wh, v1.y * wh, v1.z * wh, v1.w * wh));
}

// ---------------- launch ----------------
extern "C" void kernel_launch(void* const* d_in, const int* in_sizes, int n_in,
                              void* d_out, int out_size) {
    const float* x_op = (const float*)d_in[0];
    const float* x_m  = (const float*)d_in[1];
    const float* dtp  = (const float*)d_in[2];
    const int* ei_mp  = (const int*)d_in[3];
    const int* ei_pr  = (const int*)d_in[4];
    const int* ei_on  = (const int*)d_in[5];
    const int* ei_ho  = (const int*)d_in[6];
    const float* Wt   = (const float*)d_in[7];
    const float* bt   = (const float*)d_in[8];
    const float* lng  = (const float*)d_in[9];
    const float* lnb  = (const float*)d_in[10];
    const float* Wk   = (const float*)d_in[11];
    const float* bk   = (const float*)d_in[12];
    const float* Wq   = (const float*)d_in[13];
    const float* bq   = (const float*)d_in[14];
    const float* Wv   = (const float*)d_in[15];
    const float* bv   = (const float*)d_in[16];
    const float* Wa   = (const float*)d_in[17];
    const float* ba   = (const float*)d_in[18];
    const float* skip = (const float*)d_in[19];
    const float* a_rel = (const float*)d_in[20];
    const float* m_rel = (const float*)d_in[21];
    const float* p_rel = (const float*)d_in[22];
    float* out = (float*)d_out;

    float *p_x0, *p_proj_op, *p_proj_m, *p_wop, *p_bop, *p_wm, *p_bm;
    float *p_expa, *p_dop, *p_dm, *p_oop, *p_om;
    cudaGetSymbolAddress((void**)&p_x0, g_x0);
    cudaGetSymbolAddress((void**)&p_proj_op, g_proj_op);
    cudaGetSymbolAddress((void**)&p_proj_m, g_proj_m);
    cudaGetSymbolAddress((void**)&p_wop, g_wop);
    cudaGetSymbolAddress((void**)&p_bop, g_bop);
    cudaGetSymbolAddress((void**)&p_wm, g_wm);
    cudaGetSymbolAddress((void**)&p_bm, g_bm);
    cudaGetSymbolAddress((void**)&p_expa, g_expa);
    cudaGetSymbolAddress((void**)&p_dop, g_denom_op);
    cudaGetSymbolAddress((void**)&p_dm, g_denom_m);
    cudaGetSymbolAddress((void**)&p_oop, g_out_op);
    cudaGetSymbolAddress((void**)&p_om, g_out_m);

    int E0 = in_sizes[3] / 2, E1 = in_sizes[4] / 2, E2 = in_sizes[5] / 2, E3 = in_sizes[6] / 2;

    k_init<<<(N_OP * DD / 4 + 255) / 256, 256>>>(x_op);
    k_zero2<<<(3 * N_OP * HH + 255) / 256, 256>>>();
    k_wstack<<<LD_OP + LD_M, 256>>>(Wk, bk, Wq, bq, Wv, bv, a_rel, m_rel);
    k_temporal<<<1024, 256>>>(dtp, ei_mp, Wt, bt, lng, lnb);

    // stacked projections
    k_gemm<<<dim3(LD_OP / 128, (N_OP + 127) / 128), 256>>>(
        p_x0, p_wop, p_bop, p_proj_op, N_OP, DD, LD_OP, nullptr, nullptr, 0, 0);
    k_gemm<<<dim3(LD_M / 128, (N_M + 127) / 128), 256>>>(
        x_m, p_wm, p_bm, p_proj_m, N_M, DD, LD_M, nullptr, nullptr, 0, 0);

    // pass A
    k_edge_alpha<<<(E0 + 7) / 8, 256>>>(ei_mp, E0, p_proj_op, LD_OP, p_proj_op + 256, LD_OP,
                                        p_rel + 0, p_expa, p_dop);
    k_edge_alpha<<<(E1 + 7) / 8, 256>>>(ei_pr, E1, p_proj_op, LD_OP, p_proj_op + 512, LD_OP,
                                        p_rel + 8, p_expa + (size_t)NE * 8, p_dop + N_OP * HH);
    k_edge_alpha<<<(E2 + 7) / 8, 256>>>(ei_on, E2, p_proj_m, LD_M, p_proj_op + 768, LD_OP,
                                        p_rel + 16, p_expa + (size_t)2 * NE * 8, p_dm);
    k_edge_alpha<<<(E3 + 7) / 8, 256>>>(ei_ho, E3, p_proj_op, LD_OP, p_proj_m + 256, LD_M,
                                        p_rel + 24, p_expa + (size_t)3 * NE * 8, p_dop + 2 * N_OP * HH);

    // pass B
    k_edge_scatter<<<(E0 + 7) / 8, 256>>>(ei_mp, E0, p_proj_op + 1024, LD_OP,
                                          p_expa, p_dop, p_oop);
    k_edge_scatter<<<(E1 + 7) / 8, 256>>>(ei_pr, E1, p_proj_op + 1280, LD_OP,
                                          p_expa + (size_t)NE * 8, p_dop + N_OP * HH, p_oop);
    k_edge_scatter<<<(E2 + 7) / 8, 256>>>(ei_on, E2, p_proj_op + 1536, LD_OP,
                                          p_expa + (size_t)2 * NE * 8, p_dm, p_om);
    k_edge_scatter<<<(E3 + 7) / 8, 256>>>(ei_ho, E3, p_proj_m + 512, LD_M,
                                          p_expa + (size_t)3 * NE * 8, p_dop + 2 * N_OP * HH, p_oop);

    // final GEMMs: GELU fused into A-load, sigmoid-gated skip fused into epilogue
    k_gemm<<<dim3(256 / 128, (N_OP + 127) / 128), 256>>>(
        p_oop, Wa, ba, out, N_OP, DD, DD, p_x0, skip, 0, 1);
    k_gemm<<<dim3(256 / 128, (N_M + 127) / 128), 256>>>(
        p_om, Wa + 65536, ba + 256, out + (size_t)N_OP * DD, N_M, DD, DD, x_m, skip, 1, 1);
}

// round 4
// speedup vs baseline: 2.7223x; 1.5510x over previous
#include <cuda_runtime.h>
#include <math.h>

#define N_OP 20000
#define N_M  500
#define NE   200000
#define DD   256
#define HH   8

#define LD_OP 1792   // [q | ka0 | ka1 | ka2 | va0 | va1 | va2]
#define LD_M  768    // [q | ka3 | va3]

// ---------------- scratch ----------------
__device__ float g_x0[N_OP * DD];
__device__ float g_proj_op[(size_t)N_OP * LD_OP];
__device__ float g_proj_m[N_M * LD_M];
__device__ float g_wop[LD_OP * DD];
__device__ float g_bop[LD_OP];
__device__ float g_wm[LD_M * DD];
__device__ float g_bm[LD_M];
__device__ float g_expa[4 * (size_t)NE * HH];
__device__ float g_denom_op[3 * N_OP * HH];
__device__ float g_denom_m[N_M * HH];
__device__ float g_out_op[N_OP * DD];
__device__ float g_out_m[N_M * DD];
__device__ float g_tstat[300];            // [G 256 | a 16 | h 16 | c0 | c1]
__device__ float g_tacc[N_OP * 20];       // [rs*temb 16 | sum_rs | sum_rs_mu | cnt | pad]

__device__ __forceinline__ void red_add_v4(float* p, float4 v) {
    asm volatile("red.global.add.v4.f32 [%0], {%1,%2,%3,%4};"
                 :: "l"(p), "f"(v.x), "f"(v.y), "f"(v.z), "f"(v.w) : "memory");
}

__device__ __forceinline__ unsigned f2tf32(float f) {
    unsigned u; asm("cvt.rna.tf32.f32 %0, %1;" : "=r"(u) : "f"(f)); return u;
}

__device__ __forceinline__ void mma_tf32(float* c, unsigned a0, unsigned a1,
                                         unsigned a2, unsigned a3,
                                         unsigned b0, unsigned b1) {
    asm volatile("mma.sync.aligned.m16n8k8.row.col.f32.tf32.tf32.f32 "
                 "{%0,%1,%2,%3}, {%4,%5,%6,%7}, {%8,%9}, {%0,%1,%2,%3};"
                 : "+f"(c[0]), "+f"(c[1]), "+f"(c[2]), "+f"(c[3])
                 : "r"(a0), "r"(a1), "r"(a2), "r"(a3), "r"(b0), "r"(b1));
}

// ---------------- init ----------------
__global__ void k_init(const float* __restrict__ x_op) {
    int i = blockIdx.x * blockDim.x + threadIdx.x;
    if (i < N_OP * DD / 4) {
        ((float4*)g_x0)[i] = ((const float4*)x_op)[i];
        ((float4*)g_out_op)[i] = make_float4(0.f, 0.f, 0.f, 0.f);
    }
}

__global__ void k_zero2() {
    int i = blockIdx.x * blockDim.x + threadIdx.x;
    if (i < 3 * N_OP * HH) g_denom_op[i] = 0.f;
    if (i < N_M * DD) g_out_m[i] = 0.f;
    if (i < N_M * HH) g_denom_m[i] = 0.f;
    if (i < N_OP * 20) g_tacc[i] = 0.f;
}

// ---------------- weight stacking ----------------
__global__ void k_wstack(const float* __restrict__ Wk, const float* __restrict__ bk,
                         const float* __restrict__ Wq, const float* __restrict__ bq,
                         const float* __restrict__ Wv, const float* __restrict__ bv,
                         const float* __restrict__ a_rel, const float* __restrict__ m_rel) {
    int row = blockIdx.x;
    int in = threadIdx.x;
    float* wdst; float* bdst; int t;
    if (row < LD_OP) { wdst = g_wop; bdst = g_bop; t = 0; }
    else             { row -= LD_OP; wdst = g_wm; bdst = g_bm; t = 1; }
    int seg = row >> 8, o = row & 255;
    if (seg == 0) {
        wdst[row * DD + in] = Wq[t * 65536 + o * DD + in];
        if (in == 0) bdst[row] = bq[t * DD + o];
        return;
    }
    const float* rel; const float* Wb; const float* bb; int e;
    if (t == 0) {
        if (seg <= 3) { e = seg - 1; rel = a_rel; Wb = Wk; bb = bk; }
        else          { e = seg - 4; rel = m_rel; Wb = Wv; bb = bv; }
    } else {
        e = 3;
        if (seg == 1) { rel = a_rel; Wb = Wk; bb = bk; }
        else          { rel = m_rel; Wb = Wv; bb = bv; }
    }
    int h = o >> 5, f = o & 31;
    const float* rp = rel + ((e * 8 + h) * 32) * 32 + f;
    const float* W = Wb + t * 65536 + (h * 32) * DD;
    float acc = 0.f;
#pragma unroll 8
    for (int d = 0; d < 32; d++) acc += rp[d * 32] * W[d * DD + in];
    wdst[row * DD + in] = acc;
    if (in == 0) {
        float bacc = 0.f;
        const float* b = bb + t * DD + h * 32;
        for (int d = 0; d < 32; d++) bacc += rp[d * 32] * b[d];
        bdst[row] = bacc;
    }
}

// ---------------- temporal stats precompute ----------------
__global__ void k_tprep(const float* __restrict__ Wt, const float* __restrict__ bt) {
    __shared__ float sWt[256 * 16];
    __shared__ float sbt[256];
    int t = threadIdx.x;
    for (int i = t; i < 4096; i += 256) sWt[i] = Wt[i];
    sbt[t] = bt[t];
    __syncthreads();
    int c = t >> 4, d = t & 15;
    float acc = 0.f;
    for (int i = 0; i < 256; i++) acc += sWt[i * 16 + c] * sWt[i * 16 + d];
    g_tstat[t] = acc * (1.f / 256.f);
    if (t < 16) {
        float a = 0.f, h = 0.f;
        for (int i = 0; i < 256; i++) { a += sWt[i * 16 + t]; h += sWt[i * 16 + t] * sbt[i]; }
        g_tstat[256 + t] = a * (1.f / 256.f);
        g_tstat[272 + t] = h * (1.f / 256.f);
    }
    if (t == 0) {
        float c0 = 0.f, c1 = 0.f;
        for (int i = 0; i < 256; i++) { c0 += sbt[i]; c1 += sbt[i] * sbt[i]; }
        g_tstat[288] = c0 * (1.f / 256.f);
        g_tstat[289] = c1 * (1.f / 256.f);
    }
}

// ---------------- temporal edge pass: one thread per edge, 20-float moment scatter ----
__global__ void k_temporal2(const float* __restrict__ dtp, const int* __restrict__ ei, int E) {
    __shared__ float sG[256], sa[16], sh2[16], sc[2];
    int t = threadIdx.x;
    if (t < 256) sG[t] = g_tstat[t];
    if (t < 16) { sa[t] = g_tstat[256 + t]; sh2[t] = g_tstat[272 + t]; }
    if (t < 2) sc[t] = g_tstat[288 + t];
    __syncthreads();
    int e = blockIdx.x * blockDim.x + t;
    if (e >= E) return;
    float dt = dtp[e];
    float temb[16];
#pragma unroll
    for (int j = 0; j < 8; j++) {
        float s, c;
        sincosf(dt * exp2f(-1.2457230355827609f * (float)j), &s, &c);
        temb[2 * j] = s; temb[2 * j + 1] = c;
    }
    float mu = sc[0], hs = 0.f, q = 0.f;
#pragma unroll
    for (int c = 0; c < 16; c++) {
        mu += sa[c] * temb[c];
        hs += sh2[c] * temb[c];
        float r = 0.f;
#pragma unroll
        for (int d = 0; d < 16; d++) r += sG[c * 16 + d] * temb[d];
        q += r * temb[c];
    }
    float var = q + 2.f * hs + sc[1] - mu * mu;
    float rs = rsqrtf(var + 1e-5f);
    int src = ei[e];
    float* acc = g_tacc + (size_t)src * 20;
    red_add_v4(acc + 0,  make_float4(rs * temb[0],  rs * temb[1],  rs * temb[2],  rs * temb[3]));
    red_add_v4(acc + 4,  make_float4(rs * temb[4],  rs * temb[5],  rs * temb[6],  rs * temb[7]));
    red_add_v4(acc + 8,  make_float4(rs * temb[8],  rs * temb[9],  rs * temb[10], rs * temb[11]));
    red_add_v4(acc + 12, make_float4(rs * temb[12], rs * temb[13], rs * temb[14], rs * temb[15]));
    red_add_v4(acc + 16, make_float4(rs, rs * mu, 1.f, 0.f));
}

// ---------------- temporal finalize: x0 += g*(Wt@s16 + sr*bt - srm) + cnt*b ---------
__global__ void k_tfinal(const float* __restrict__ Wt, const float* __restrict__ bt,
                         const float* __restrict__ lng, const float* __restrict__ lnb) {
    __shared__ float s[20];
    int n = blockIdx.x, t = threadIdx.x;
    if (t < 20) s[t] = g_tacc[(size_t)n * 20 + t];
    __syncthreads();
    float cnt = s[18];
    if (cnt == 0.f) return;
    float sr = s[16], srm = s[17];
    const float4* wr = (const float4*)(Wt + t * 16);
    float4 w0 = wr[0], w1 = wr[1], w2 = wr[2], w3 = wr[3];
    float acc = w0.x * s[0] + w0.y * s[1] + w0.z * s[2] + w0.w * s[3]
              + w1.x * s[4] + w1.y * s[5] + w1.z * s[6] + w1.w * s[7]
              + w2.x * s[8] + w2.y * s[9] + w2.z * s[10] + w2.w * s[11]
              + w3.x * s[12] + w3.y * s[13] + w3.z * s[14] + w3.w * s[15];
    float y = lng[t] * (acc + sr * bt[t] - srm) + cnt * lnb[t];
    g_x0[(size_t)n * DD + t] += y;
}

// ---------------- tf32 tensor-core GEMM: C = A[M,256] @ W[N,256]^T + bias ----------
// 128x128 block tile, 8 warps of 64x32, K-slab 32.  N multiple of 128, K == 256.
__global__ void __launch_bounds__(256, 2)
k_gemm_tf32(const float* __restrict__ A, const float* __restrict__ W,
            const float* __restrict__ bias, float* __restrict__ C,
            int M, int lda, int ldc,
            const float* __restrict__ skipX, const float* __restrict__ skipP,
            int skipIdx, int geluA) {
    __shared__ unsigned sA[128][36];
    __shared__ unsigned sW[128][36];
    int tid = threadIdx.x;
    int lane = tid & 31, wid = tid >> 5;
    int gID = lane >> 2, tig = lane & 3;
    int mw = (wid >> 2) * 64, nw = (wid & 3) * 32;
    int m0 = blockIdx.y * 128, n0 = blockIdx.x * 128;
    int lr = tid >> 1;
    int lc0 = (tid & 1) * 16;
    float acc[4][4][4];
#pragma unroll
    for (int i = 0; i < 4; i++)
#pragma unroll
        for (int j = 0; j < 4; j++)
#pragma unroll
            for (int r = 0; r < 4; r++) acc[i][j][r] = 0.f;

    for (int k0 = 0; k0 < 256; k0 += 32) {
        int gm = m0 + lr;
#pragma unroll
        for (int j = 0; j < 4; j++) {
            float4 v = make_float4(0.f, 0.f, 0.f, 0.f);
            if (gm < M) v = *(const float4*)&A[(size_t)gm * lda + k0 + lc0 + j * 4];
            if (geluA) {
                v.x = 0.5f * v.x * (1.f + erff(v.x * 0.70710678118654752f));
                v.y = 0.5f * v.y * (1.f + erff(v.y * 0.70710678118654752f));
                v.z = 0.5f * v.z * (1.f + erff(v.z * 0.70710678118654752f));
                v.w = 0.5f * v.w * (1.f + erff(v.w * 0.70710678118654752f));
            }
            sA[lr][lc0 + 4 * j + 0] = f2tf32(v.x);
            sA[lr][lc0 + 4 * j + 1] = f2tf32(v.y);
            sA[lr][lc0 + 4 * j + 2] = f2tf32(v.z);
            sA[lr][lc0 + 4 * j + 3] = f2tf32(v.w);
        }
#pragma unroll
        for (int j = 0; j < 4; j++) {
            float4 v = *(const float4*)&W[(size_t)(n0 + lr) * 256 + k0 + lc0 + j * 4];
            sW[lr][lc0 + 4 * j + 0] = f2tf32(v.x);
            sW[lr][lc0 + 4 * j + 1] = f2tf32(v.y);
            sW[lr][lc0 + 4 * j + 2] = f2tf32(v.z);
            sW[lr][lc0 + 4 * j + 3] = f2tf32(v.w);
        }
        __syncthreads();
#pragma unroll
        for (int kk = 0; kk < 32; kk += 8) {
            unsigned bfr[4][2];
#pragma unroll
            for (int nt = 0; nt < 4; nt++) {
                int n = nw + nt * 8 + gID;
                bfr[nt][0] = sW[n][kk + tig];
                bfr[nt][1] = sW[n][kk + tig + 4];
            }
#pragma unroll
            for (int mt = 0; mt < 4; mt++) {
                int m = mw + mt * 16 + gID;
                unsigned a0 = sA[m][kk + tig];
                unsigned a1 = sA[m + 8][kk + tig];
                unsigned a2 = sA[m][kk + tig + 4];
                unsigned a3 = sA[m + 8][kk + tig + 4];
#pragma unroll
                for (int nt = 0; nt < 4; nt++)
                    mma_tf32(acc[mt][nt], a0, a1, a2, a3, bfr[nt][0], bfr[nt][1]);
            }
        }
        __syncthreads();
    }

    bool hs = (skipX != nullptr);
    float sa = 0.f, sb2 = 0.f;
    if (hs) { float s = skipP[skipIdx]; sa = 1.f / (1.f + __expf(-s)); sb2 = 1.f - sa; }
#pragma unroll
    for (int mt = 0; mt < 4; mt++) {
#pragma unroll
        for (int half = 0; half < 2; half++) {
            int m = m0 + mw + mt * 16 + gID + half * 8;
            if (m < M) {
#pragma unroll
                for (int nt = 0; nt < 4; nt++) {
                    int n = n0 + nw + nt * 8 + tig * 2;
                    float v0 = acc[mt][nt][half * 2 + 0] + bias[n];
                    float v1 = acc[mt][nt][half * 2 + 1] + bias[n + 1];
                    if (hs) {
                        v0 = sa * v0 + sb2 * skipX[(size_t)m * DD + n];
                        v1 = sa * v1 + sb2 * skipX[(size_t)m * DD + n + 1];
                    }
                    *(float2*)&C[(size_t)m * ldc + n] = make_float2(v0, v1);
                }
            }
        }
    }
}

// ---------------- edge pass A: alpha -> expa, denom ----------------
__global__ void k_edge_alpha(const int* __restrict__ ei, int E,
                             const float* __restrict__ qb, int qld,
                             const float* __restrict__ kb, int kld,
                             const float* __restrict__ prel,
                             float* __restrict__ expa, float* __restrict__ denom) {
    int w = (blockIdx.x * blockDim.x + threadIdx.x) >> 5;
    if (w >= E) return;
    int lane = threadIdx.x & 31;
    int src = ei[w], dst = ei[E + w];
    const float4* q = (const float4*)(qb + (size_t)dst * qld);
    const float4* k = (const float4*)(kb + (size_t)src * kld);
    float4 q0 = q[lane * 2], q1 = q[lane * 2 + 1];
    float4 k0 = k[lane * 2], k1 = k[lane * 2 + 1];
    float p = q0.x * k0.x + q0.y * k0.y + q0.z * k0.z + q0.w * k0.w
            + q1.x * k1.x + q1.y * k1.y + q1.z * k1.z + q1.w * k1.w;
    p += __shfl_xor_sync(0xffffffffu, p, 1);
    p += __shfl_xor_sync(0xffffffffu, p, 2);
    float v = __shfl_sync(0xffffffffu, p, (lane * 4) & 31);
    if (lane < 8) {
        float ex = __expf(v * prel[lane] * 0.17677669529663687f);
        expa[(size_t)w * 8 + lane] = ex;
        atomicAdd(&denom[(size_t)dst * 8 + lane], ex);
    }
}

// ---------------- edge pass B: scatter v * softmax-weight (vector REDs) ----------------
__global__ void k_edge_scatter(const int* __restrict__ ei, int E,
                               const float* __restrict__ vb, int vld,
                               const float* __restrict__ expa, const float* __restrict__ denom,
                               float* __restrict__ out) {
    int w = (blockIdx.x * blockDim.x + threadIdx.x) >> 5;
    if (w >= E) return;
    int lane = threadIdx.x & 31;
    int src = ei[w], dst = ei[E + w];
    float wgt = 0.f;
    if (lane < 8) wgt = expa[(size_t)w * 8 + lane] / denom[(size_t)dst * 8 + lane];
    float wh = __shfl_sync(0xffffffffu, wgt, lane >> 2);
    const float4* v = (const float4*)(vb + (size_t)src * vld);
    float4 v0 = v[lane * 2], v1 = v[lane * 2 + 1];
    float* o = out + (size_t)dst * DD + lane * 8;
    red_add_v4(o, make_float4(v0.x * wh, v0.y * wh, v0.z * wh, v0.w * wh));
    red_add_v4(o + 4, make_float4(v1.x * wh, v1.y * wh, v1.z * wh, v1.w * wh));
}

// ---------------- launch ----------------
extern "C" void kernel_launch(void* const* d_in, const int* in_sizes, int n_in,
                              void* d_out, int out_size) {
    const float* x_op = (const float*)d_in[0];
    const float* x_m  = (const float*)d_in[1];
    const float* dtp  = (const float*)d_in[2];
    const int* ei_mp  = (const int*)d_in[3];
    const int* ei_pr  = (const int*)d_in[4];
    const int* ei_on  = (const int*)d_in[5];
    const int* ei_ho  = (const int*)d_in[6];
    const float* Wt   = (const float*)d_in[7];
    const float* bt   = (const float*)d_in[8];
    const float* lng  = (const float*)d_in[9];
    const float* lnb  = (const float*)d_in[10];
    const float* Wk   = (const float*)d_in[11];
    const float* bk   = (const float*)d_in[12];
    const float* Wq   = (const float*)d_in[13];
    const float* bq   = (const float*)d_in[14];
    const float* Wv   = (const float*)d_in[15];
    const float* bv   = (const float*)d_in[16];
    const float* Wa   = (const float*)d_in[17];
    const float* ba   = (const float*)d_in[18];
    const float* skip = (const float*)d_in[19];
    const float* a_rel = (const float*)d_in[20];
    const float* m_rel = (const float*)d_in[21];
    const float* p_rel = (const float*)d_in[22];
    float* out = (float*)d_out;

    float *p_x0, *p_proj_op, *p_proj_m, *p_wop, *p_bop, *p_wm, *p_bm;
    float *p_expa, *p_dop, *p_dm, *p_oop, *p_om;
    cudaGetSymbolAddress((void**)&p_x0, g_x0);
    cudaGetSymbolAddress((void**)&p_proj_op, g_proj_op);
    cudaGetSymbolAddress((void**)&p_proj_m, g_proj_m);
    cudaGetSymbolAddress((void**)&p_wop, g_wop);
    cudaGetSymbolAddress((void**)&p_bop, g_bop);
    cudaGetSymbolAddress((void**)&p_wm, g_wm);
    cudaGetSymbolAddress((void**)&p_bm, g_bm);
    cudaGetSymbolAddress((void**)&p_expa, g_expa);
    cudaGetSymbolAddress((void**)&p_dop, g_denom_op);
    cudaGetSymbolAddress((void**)&p_dm, g_denom_m);
    cudaGetSymbolAddress((void**)&p_oop, g_out_op);
    cudaGetSymbolAddress((void**)&p_om, g_out_m);

    int E0 = in_sizes[3] / 2, E1 = in_sizes[4] / 2, E2 = in_sizes[5] / 2, E3 = in_sizes[6] / 2;

    k_init<<<(N_OP * DD / 4 + 255) / 256, 256>>>(x_op);
    k_zero2<<<(3 * N_OP * HH + 255) / 256, 256>>>();
    k_wstack<<<LD_OP + LD_M, 256>>>(Wk, bk, Wq, bq, Wv, bv, a_rel, m_rel);
    k_tprep<<<1, 256>>>(Wt, bt);
    k_temporal2<<<(E0 + 255) / 256, 256>>>(dtp, ei_mp, E0);
    k_tfinal<<<N_OP, 256>>>(Wt, bt, lng, lnb);

    // stacked projections (tf32 tensor cores)
    k_gemm_tf32<<<dim3(LD_OP / 128, (N_OP + 127) / 128), 256>>>(
        p_x0, p_wop, p_bop, p_proj_op, N_OP, DD, LD_OP, nullptr, nullptr, 0, 0);
    k_gemm_tf32<<<dim3(LD_M / 128, (N_M + 127) / 128), 256>>>(
        x_m, p_wm, p_bm, p_proj_m, N_M, DD, LD_M, nullptr, nullptr, 0, 0);

    // pass A
    k_edge_alpha<<<(E0 + 7) / 8, 256>>>(ei_mp, E0, p_proj_op, LD_OP, p_proj_op + 256, LD_OP,
                                        p_rel + 0, p_expa, p_dop);
    k_edge_alpha<<<(E1 + 7) / 8, 256>>>(ei_pr, E1, p_proj_op, LD_OP, p_proj_op + 512, LD_OP,
                                        p_rel + 8, p_expa + (size_t)NE * 8, p_dop + N_OP * HH);
    k_edge_alpha<<<(E2 + 7) / 8, 256>>>(ei_on, E2, p_proj_m, LD_M, p_proj_op + 768, LD_OP,
                                        p_rel + 16, p_expa + (size_t)2 * NE * 8, p_dm);
    k_edge_alpha<<<(E3 + 7) / 8, 256>>>(ei_ho, E3, p_proj_op, LD_OP, p_proj_m + 256, LD_M,
                                        p_rel + 24, p_expa + (size_t)3 * NE * 8, p_dop + 2 * N_OP * HH);

    // pass B
    k_edge_scatter<<<(E0 + 7) / 8, 256>>>(ei_mp, E0, p_proj_op + 1024, LD_OP,
                                          p_expa, p_dop, p_oop);
    k_edge_scatter<<<(E1 + 7) / 8, 256>>>(ei_pr, E1, p_proj_op + 1280, LD_OP,
                                          p_expa + (size_t)NE * 8, p_dop + N_OP * HH, p_oop);
    k_edge_scatter<<<(E2 + 7) / 8, 256>>>(ei_on, E2, p_proj_op + 1536, LD_OP,
                                          p_expa + (size_t)2 * NE * 8, p_dm, p_om);
    k_edge_scatter<<<(E3 + 7) / 8, 256>>>(ei_ho, E3, p_proj_m + 512, LD_M,
                                          p_expa + (size_t)3 * NE * 8, p_dop + 2 * N_OP * HH, p_oop);

    // final GEMMs: GELU fused into A-load, sigmoid-gated skip fused into epilogue
    k_gemm_tf32<<<dim3(DD / 128, (N_OP + 127) / 128), 256>>>(
        p_oop, Wa, ba, out, N_OP, DD, DD, p_x0, skip, 0, 1);
    k_gemm_tf32<<<dim3(DD / 128, (N_M + 127) / 128), 256>>>(
        p_om, Wa + 65536, ba + 256, out + (size_t)N_OP * DD, N_M, DD, DD, x_m, skip, 1, 1);
}

// round 5
// speedup vs baseline: 2.9162x; 1.0712x over previous
#include <cuda_runtime.h>
#include <math.h>

#define N_OP 20000
#define N_M  500
#define NE   200000
#define DD   256
#define HH   8

#define LD_OP 1792   // [q | ka0 | ka1 | ka2 | va0 | va1 | va2]
#define LD_M  768    // [q | ka3 | va3]

// ---------------- scratch ----------------
__device__ float g_x0[N_OP * DD];
__device__ float g_proj_op[(size_t)N_OP * LD_OP];
__device__ float g_proj_m[N_M * LD_M];
__device__ float g_wop[LD_OP * DD];
__device__ float g_bop[LD_OP];
__device__ float g_wm[LD_M * DD];
__device__ float g_bm[LD_M];
__device__ float g_denom_op[3 * N_OP * HH];   // type slots 0,1,3
__device__ float g_denom_m[N_M * HH];
__device__ float g_acc0[N_OP * DD];           // unnormalized per-type sums
__device__ float g_acc1[N_OP * DD];
__device__ float g_acc3[N_OP * DD];
__device__ float g_accm[N_M * DD];
__device__ float g_out_op[N_OP * DD];
__device__ float g_out_m[N_M * DD];
__device__ float g_tstat[300];                // [G 256 | a 16 | h 16 | c0 | c1]
__device__ float g_tacc[N_OP * 20];           // [rs*temb 16 | sum_rs | sum_rs_mu | cnt | pad]

__device__ __forceinline__ void red_add_v4(float* p, float4 v) {
    asm volatile("red.global.add.v4.f32 [%0], {%1,%2,%3,%4};"
                 :: "l"(p), "f"(v.x), "f"(v.y), "f"(v.z), "f"(v.w) : "memory");
}

__device__ __forceinline__ unsigned f2tf32(float f) {
    unsigned u; asm("cvt.rna.tf32.f32 %0, %1;" : "=r"(u) : "f"(f)); return u;
}

__device__ __forceinline__ void mma_tf32(float* c, unsigned a0, unsigned a1,
                                         unsigned a2, unsigned a3,
                                         unsigned b0, unsigned b1) {
    asm volatile("mma.sync.aligned.m16n8k8.row.col.f32.tf32.tf32.f32 "
                 "{%0,%1,%2,%3}, {%4,%5,%6,%7}, {%8,%9}, {%0,%1,%2,%3};"
                 : "+f"(c[0]), "+f"(c[1]), "+f"(c[2]), "+f"(c[3])
                 : "r"(a0), "r"(a1), "r"(a2), "r"(a3), "r"(b0), "r"(b1));
}

// ---------------- init / zero ----------------
__global__ void k_init(const float* __restrict__ x_op) {
    int i = blockIdx.x * blockDim.x + threadIdx.x;
    if (i < N_OP * DD / 4) ((float4*)g_x0)[i] = ((const float4*)x_op)[i];
}

__global__ void k_zero() {
    int i = blockIdx.x * blockDim.x + threadIdx.x;
    float4 z = make_float4(0.f, 0.f, 0.f, 0.f);
    if (i < N_OP * DD / 4) {
        ((float4*)g_acc0)[i] = z;
        ((float4*)g_acc1)[i] = z;
        ((float4*)g_acc3)[i] = z;
    }
    if (i < N_M * DD / 4) ((float4*)g_accm)[i] = z;
    if (i < 3 * N_OP * HH / 4) ((float4*)g_denom_op)[i] = z;
    if (i < N_M * HH / 4) ((float4*)g_denom_m)[i] = z;
    if (i < N_OP * 20 / 4) ((float4*)g_tacc)[i] = z;
}

// ---------------- weight stacking ----------------
__global__ void k_wstack(const float* __restrict__ Wk, const float* __restrict__ bk,
                         const float* __restrict__ Wq, const float* __restrict__ bq,
                         const float* __restrict__ Wv, const float* __restrict__ bv,
                         const float* __restrict__ a_rel, const float* __restrict__ m_rel) {
    int row = blockIdx.x;
    int in = threadIdx.x;
    float* wdst; float* bdst; int t;
    if (row < LD_OP) { wdst = g_wop; bdst = g_bop; t = 0; }
    else             { row -= LD_OP; wdst = g_wm; bdst = g_bm; t = 1; }
    int seg = row >> 8, o = row & 255;
    if (seg == 0) {
        wdst[row * DD + in] = Wq[t * 65536 + o * DD + in];
        if (in == 0) bdst[row] = bq[t * DD + o];
        return;
    }
    const float* rel; const float* Wb; const float* bb; int e;
    if (t == 0) {
        if (seg <= 3) { e = seg - 1; rel = a_rel; Wb = Wk; bb = bk; }
        else          { e = seg - 4; rel = m_rel; Wb = Wv; bb = bv; }
    } else {
        e = 3;
        if (seg == 1) { rel = a_rel; Wb = Wk; bb = bk; }
        else          { rel = m_rel; Wb = Wv; bb = bv; }
    }
    int h = o >> 5, f = o & 31;
    const float* rp = rel + ((e * 8 + h) * 32) * 32 + f;
    const float* W = Wb + t * 65536 + (h * 32) * DD;
    float acc = 0.f;
#pragma unroll 8
    for (int d = 0; d < 32; d++) acc += rp[d * 32] * W[d * DD + in];
    wdst[row * DD + in] = acc;
    if (in == 0) {
        float bacc = 0.f;
        const float* b = bb + t * DD + h * 32;
        for (int d = 0; d < 32; d++) bacc += rp[d * 32] * b[d];
        bdst[row] = bacc;
    }
}

// ---------------- temporal stats precompute (parallel over 257 blocks) ----------------
__global__ void k_tprep(const float* __restrict__ Wt, const float* __restrict__ bt) {
    __shared__ float red[256];
    int b = blockIdx.x, t = threadIdx.x;
    float val;
    if (b < 256) {          // G[c][d]
        int c = b >> 4, d = b & 15;
        val = Wt[t * 16 + c] * Wt[t * 16 + d];
    } else {                // block 256: handled below per-thread group
        val = 0.f;
    }
    if (b == 256) {
        // threads 0-255 unused for reduction; compute a,h,c0,c1 serially-parallel
        // a[j] = mean_i Wt[i][j]; h[j] = mean_i Wt[i][j]*bt[i]; c0=mean bt; c1=mean bt^2
        if (t < 16) {
            float a = 0.f, h = 0.f;
            for (int i = 0; i < 256; i++) {
                float w = Wt[i * 16 + t];
                a += w; h += w * bt[i];
            }
            g_tstat[256 + t] = a * (1.f / 256.f);
            g_tstat[272 + t] = h * (1.f / 256.f);
        } else if (t == 16) {
            float c0 = 0.f, c1 = 0.f;
            for (int i = 0; i < 256; i++) { c0 += bt[i]; c1 += bt[i] * bt[i]; }
            g_tstat[288] = c0 * (1.f / 256.f);
            g_tstat[289] = c1 * (1.f / 256.f);
        }
        return;
    }
    red[t] = val;
    __syncthreads();
    for (int o = 128; o; o >>= 1) {
        if (t < o) red[t] += red[t + o];
        __syncthreads();
    }
    if (t == 0) g_tstat[b] = red[0] * (1.f / 256.f);
}

// ---------------- temporal edge pass: one thread per edge, 20-float moment scatter ----
__global__ void k_temporal2(const float* __restrict__ dtp, const int* __restrict__ ei, int E) {
    __shared__ float sG[256], sa[16], sh2[16], sc[2];
    int t = threadIdx.x;
    if (t < 256) sG[t] = g_tstat[t];
    if (t < 16) { sa[t] = g_tstat[256 + t]; sh2[t] = g_tstat[272 + t]; }
    if (t < 2) sc[t] = g_tstat[288 + t];
    __syncthreads();
    int e = blockIdx.x * blockDim.x + t;
    if (e >= E) return;
    float dt = dtp[e];
    float temb[16];
#pragma unroll
    for (int j = 0; j < 8; j++) {
        float s, c;
        sincosf(dt * exp2f(-1.2457230355827609f * (float)j), &s, &c);
        temb[2 * j] = s; temb[2 * j + 1] = c;
    }
    float mu = sc[0], hs = 0.f, q = 0.f;
#pragma unroll
    for (int c = 0; c < 16; c++) {
        mu += sa[c] * temb[c];
        hs += sh2[c] * temb[c];
        float r = 0.f;
#pragma unroll
        for (int d = 0; d < 16; d++) r += sG[c * 16 + d] * temb[d];
        q += r * temb[c];
    }
    float var = q + 2.f * hs + sc[1] - mu * mu;
    float rs = rsqrtf(var + 1e-5f);
    int src = ei[e];
    float* acc = g_tacc + (size_t)src * 20;
    red_add_v4(acc + 0,  make_float4(rs * temb[0],  rs * temb[1],  rs * temb[2],  rs * temb[3]));
    red_add_v4(acc + 4,  make_float4(rs * temb[4],  rs * temb[5],  rs * temb[6],  rs * temb[7]));
    red_add_v4(acc + 8,  make_float4(rs * temb[8],  rs * temb[9],  rs * temb[10], rs * temb[11]));
    red_add_v4(acc + 12, make_float4(rs * temb[12], rs * temb[13], rs * temb[14], rs * temb[15]));
    red_add_v4(acc + 16, make_float4(rs, rs * mu, 1.f, 0.f));
}

// ---------------- temporal finalize: x0 += g*(Wt@s16 + sr*bt - srm) + cnt*b ---------
__global__ void k_tfinal(const float* __restrict__ Wt, const float* __restrict__ bt,
                         const float* __restrict__ lng, const float* __restrict__ lnb) {
    __shared__ float s[20];
    int n = blockIdx.x, t = threadIdx.x;
    if (t < 20) s[t] = g_tacc[(size_t)n * 20 + t];
    __syncthreads();
    float cnt = s[18];
    if (cnt == 0.f) return;
    float sr = s[16], srm = s[17];
    const float4* wr = (const float4*)(Wt + t * 16);
    float4 w0 = wr[0], w1 = wr[1], w2 = wr[2], w3 = wr[3];
    float acc = w0.x * s[0] + w0.y * s[1] + w0.z * s[2] + w0.w * s[3]
              + w1.x * s[4] + w1.y * s[5] + w1.z * s[6] + w1.w * s[7]
              + w2.x * s[8] + w2.y * s[9] + w2.z * s[10] + w2.w * s[11]
              + w3.x * s[12] + w3.y * s[13] + w3.z * s[14] + w3.w * s[15];
    float y = lng[t] * (acc + sr * bt[t] - srm) + cnt * lnb[t];
    g_x0[(size_t)n * DD + t] += y;
}

// ---------------- tf32 tensor-core GEMM: C = A[M,256] @ W[N,256]^T + bias ----------
__global__ void __launch_bounds__(256, 2)
k_gemm_tf32(const float* __restrict__ A, const float* __restrict__ W,
            const float* __restrict__ bias, float* __restrict__ C,
            int M, int lda, int ldc,
            const float* __restrict__ skipX, const float* __restrict__ skipP,
            int skipIdx) {
    __shared__ unsigned sA[128][36];
    __shared__ unsigned sW[128][36];
    int tid = threadIdx.x;
    int lane = tid & 31, wid = tid >> 5;
    int gID = lane >> 2, tig = lane & 3;
    int mw = (wid >> 2) * 64, nw = (wid & 3) * 32;
    int m0 = blockIdx.y * 128, n0 = blockIdx.x * 128;
    int lr = tid >> 1;
    int lc0 = (tid & 1) * 16;
    float acc[4][4][4];
#pragma unroll
    for (int i = 0; i < 4; i++)
#pragma unroll
        for (int j = 0; j < 4; j++)
#pragma unroll
            for (int r = 0; r < 4; r++) acc[i][j][r] = 0.f;

    for (int k0 = 0; k0 < 256; k0 += 32) {
        int gm = m0 + lr;
#pragma unroll
        for (int j = 0; j < 4; j++) {
            float4 v = make_float4(0.f, 0.f, 0.f, 0.f);
            if (gm < M) v = *(const float4*)&A[(size_t)gm * lda + k0 + lc0 + j * 4];
            sA[lr][lc0 + 4 * j + 0] = f2tf32(v.x);
            sA[lr][lc0 + 4 * j + 1] = f2tf32(v.y);
            sA[lr][lc0 + 4 * j + 2] = f2tf32(v.z);
            sA[lr][lc0 + 4 * j + 3] = f2tf32(v.w);
        }
#pragma unroll
        for (int j = 0; j < 4; j++) {
            float4 v = *(const float4*)&W[(size_t)(n0 + lr) * 256 + k0 + lc0 + j * 4];
            sW[lr][lc0 + 4 * j + 0] = f2tf32(v.x);
            sW[lr][lc0 + 4 * j + 1] = f2tf32(v.y);
            sW[lr][lc0 + 4 * j + 2] = f2tf32(v.z);
            sW[lr][lc0 + 4 * j + 3] = f2tf32(v.w);
        }
        __syncthreads();
#pragma unroll
        for (int kk = 0; kk < 32; kk += 8) {
            unsigned bfr[4][2];
#pragma unroll
            for (int nt = 0; nt < 4; nt++) {
                int n = nw + nt * 8 + gID;
                bfr[nt][0] = sW[n][kk + tig];
                bfr[nt][1] = sW[n][kk + tig + 4];
            }
#pragma unroll
            for (int mt = 0; mt < 4; mt++) {
                int m = mw + mt * 16 + gID;
                unsigned a0 = sA[m][kk + tig];
                unsigned a1 = sA[m + 8][kk + tig];
                unsigned a2 = sA[m][kk + tig + 4];
                unsigned a3 = sA[m + 8][kk + tig + 4];
#pragma unroll
                for (int nt = 0; nt < 4; nt++)
                    mma_tf32(acc[mt][nt], a0, a1, a2, a3, bfr[nt][0], bfr[nt][1]);
            }
        }
        __syncthreads();
    }

    bool hs = (skipX != nullptr);
    float sa = 0.f, sb2 = 0.f;
    if (hs) { float s = skipP[skipIdx]; sa = 1.f / (1.f + __expf(-s)); sb2 = 1.f - sa; }
#pragma unroll
    for (int mt = 0; mt < 4; mt++) {
#pragma unroll
        for (int half = 0; half < 2; half++) {
            int m = m0 + mw + mt * 16 + gID + half * 8;
            if (m < M) {
#pragma unroll
                for (int nt = 0; nt < 4; nt++) {
                    int n = n0 + nw + nt * 8 + tig * 2;
                    float v0 = acc[mt][nt][half * 2 + 0] + bias[n];
                    float v1 = acc[mt][nt][half * 2 + 1] + bias[n + 1];
                    if (hs) {
                        v0 = sa * v0 + sb2 * skipX[(size_t)m * DD + n];
                        v1 = sa * v1 + sb2 * skipX[(size_t)m * DD + n + 1];
                    }
                    *(float2*)&C[(size_t)m * ldc + n] = make_float2(v0, v1);
                }
            }
        }
    }
}

// ---------------- fused edge pass: alpha -> exp -> unnormalized scatter + denom ------
// one warp per edge.  kvb row holds both k (at 0) and v (at vofs).
__global__ void k_edge_fused(const int* __restrict__ ei, int E,
                             const float* __restrict__ qb, int qld,
                             const float* __restrict__ kvb, int kvld, int vofs,
                             const float* __restrict__ prel,
                             float* __restrict__ denom, float* __restrict__ out) {
    int w = (blockIdx.x * blockDim.x + threadIdx.x) >> 5;
    if (w >= E) return;
    int lane = threadIdx.x & 31;
    int src = ei[w], dst = ei[E + w];
    const float4* q = (const float4*)(qb + (size_t)dst * qld);
    const float4* k = (const float4*)(kvb + (size_t)src * kvld);
    const float4* v = (const float4*)(kvb + (size_t)src * kvld + vofs);
    float4 q0 = q[lane * 2], q1 = q[lane * 2 + 1];
    float4 k0 = k[lane * 2], k1 = k[lane * 2 + 1];
    float4 v0 = v[lane * 2], v1 = v[lane * 2 + 1];
    float p = q0.x * k0.x + q0.y * k0.y + q0.z * k0.z + q0.w * k0.w
            + q1.x * k1.x + q1.y * k1.y + q1.z * k1.z + q1.w * k1.w;
    p += __shfl_xor_sync(0xffffffffu, p, 1);
    p += __shfl_xor_sync(0xffffffffu, p, 2);
    float a = __shfl_sync(0xffffffffu, p, (lane * 4) & 31);   // lane h<8: head h dot
    float ex = 0.f;
    if (lane < 8) ex = __expf(a * prel[lane] * 0.17677669529663687f);
    float wh = __shfl_sync(0xffffffffu, ex, lane >> 2);       // per-lane head weight
    float* o = out + (size_t)dst * DD + lane * 8;
    red_add_v4(o, make_float4(v0.x * wh, v0.y * wh, v0.z * wh, v0.w * wh));
    red_add_v4(o + 4, make_float4(v1.x * wh, v1.y * wh, v1.z * wh, v1.w * wh));
    if (lane < 8) atomicAdd(&denom[(size_t)dst * 8 + lane], ex);
}

// ---------------- finalize: divide by denoms, sum types, exact GELU ----------------
__global__ void k_final_op() {
    int i = blockIdx.x * blockDim.x + threadIdx.x;
    if (i >= N_OP * DD) return;
    int n = i >> 8, h = (i & 255) >> 5;
    float val = 0.f, d;
    d = g_denom_op[n * 8 + h];                 if (d > 0.f) val += g_acc0[i] / d;
    d = g_denom_op[N_OP * 8 + n * 8 + h];      if (d > 0.f) val += g_acc1[i] / d;
    d = g_denom_op[2 * N_OP * 8 + n * 8 + h];  if (d > 0.f) val += g_acc3[i] / d;
    g_out_op[i] = 0.5f * val * (1.f + erff(val * 0.70710678118654752f));
}

__global__ void k_final_m() {
    int i = blockIdx.x * blockDim.x + threadIdx.x;
    if (i >= N_M * DD) return;
    int n = i >> 8, h = (i & 255) >> 5;
    float val = 0.f;
    float d = g_denom_m[n * 8 + h];
    if (d > 0.f) val = g_accm[i] / d;
    g_out_m[i] = 0.5f * val * (1.f + erff(val * 0.70710678118654752f));
}

// ---------------- launch ----------------
extern "C" void kernel_launch(void* const* d_in, const int* in_sizes, int n_in,
                              void* d_out, int out_size) {
    const float* x_op = (const float*)d_in[0];
    const float* x_m  = (const float*)d_in[1];
    const float* dtp  = (const float*)d_in[2];
    const int* ei_mp  = (const int*)d_in[3];
    const int* ei_pr  = (const int*)d_in[4];
    const int* ei_on  = (const int*)d_in[5];
    const int* ei_ho  = (const int*)d_in[6];
    const float* Wt   = (const float*)d_in[7];
    const float* bt   = (const float*)d_in[8];
    const float* lng  = (const float*)d_in[9];
    const float* lnb  = (const float*)d_in[10];
    const float* Wk   = (const float*)d_in[11];
    const float* bk   = (const float*)d_in[12];
    const float* Wq   = (const float*)d_in[13];
    const float* bq   = (const float*)d_in[14];
    const float* Wv   = (const float*)d_in[15];
    const float* bv   = (const float*)d_in[16];
    const float* Wa   = (const float*)d_in[17];
    const float* ba   = (const float*)d_in[18];
    const float* skip = (const float*)d_in[19];
    const float* a_rel = (const float*)d_in[20];
    const float* m_rel = (const float*)d_in[21];
    const float* p_rel = (const float*)d_in[22];
    float* out = (float*)d_out;

    float *p_x0, *p_proj_op, *p_proj_m, *p_wop, *p_bop, *p_wm, *p_bm;
    float *p_dop, *p_dm, *p_oop, *p_om, *p_a0, *p_a1, *p_a3, *p_am;
    cudaGetSymbolAddress((void**)&p_x0, g_x0);
    cudaGetSymbolAddress((void**)&p_proj_op, g_proj_op);
    cudaGetSymbolAddress((void**)&p_proj_m, g_proj_m);
    cudaGetSymbolAddress((void**)&p_wop, g_wop);
    cudaGetSymbolAddress((void**)&p_bop, g_bop);
    cudaGetSymbolAddress((void**)&p_wm, g_wm);
    cudaGetSymbolAddress((void**)&p_bm, g_bm);
    cudaGetSymbolAddress((void**)&p_dop, g_denom_op);
    cudaGetSymbolAddress((void**)&p_dm, g_denom_m);
    cudaGetSymbolAddress((void**)&p_oop, g_out_op);
    cudaGetSymbolAddress((void**)&p_om, g_out_m);
    cudaGetSymbolAddress((void**)&p_a0, g_acc0);
    cudaGetSymbolAddress((void**)&p_a1, g_acc1);
    cudaGetSymbolAddress((void**)&p_a3, g_acc3);
    cudaGetSymbolAddress((void**)&p_am, g_accm);

    int E0 = in_sizes[3] / 2, E1 = in_sizes[4] / 2, E2 = in_sizes[5] / 2, E3 = in_sizes[6] / 2;

    k_init<<<(N_OP * DD / 4 + 255) / 256, 256>>>(x_op);
    k_zero<<<(N_OP * DD / 4 + 255) / 256, 256>>>();
    k_wstack<<<LD_OP + LD_M, 256>>>(Wk, bk, Wq, bq, Wv, bv, a_rel, m_rel);
    k_tprep<<<257, 256>>>(Wt, bt);
    k_temporal2<<<(E0 + 255) / 256, 256>>>(dtp, ei_mp, E0);
    k_tfinal<<<N_OP, 256>>>(Wt, bt, lng, lnb);

    // stacked projections (tf32 tensor cores)
    k_gemm_tf32<<<dim3(LD_OP / 128, (N_OP + 127) / 128), 256>>>(
        p_x0, p_wop, p_bop, p_proj_op, N_OP, DD, LD_OP, nullptr, nullptr, 0);
    k_gemm_tf32<<<dim3(LD_M / 128, (N_M + 127) / 128), 256>>>(
        x_m, p_wm, p_bm, p_proj_m, N_M, DD, LD_M, nullptr, nullptr, 0);

    // fused edge passes: unnormalized scatter + denominators
    // type 0 (mp, op->op):   k seg 256,  v seg 1024 (vofs 768)
    k_edge_fused<<<(E0 + 7) / 8, 256>>>(ei_mp, E0, p_proj_op, LD_OP,
                                        p_proj_op + 256, LD_OP, 768,
                                        p_rel + 0, p_dop, p_a0);
    // type 1 (prec, op->op): k seg 512,  v seg 1280
    k_edge_fused<<<(E1 + 7) / 8, 256>>>(ei_pr, E1, p_proj_op, LD_OP,
                                        p_proj_op + 512, LD_OP, 768,
                                        p_rel + 8, p_dop + N_OP * HH, p_a1);
    // type 2 (on, op->m):    k seg 768,  v seg 1536;  q from machines
    k_edge_fused<<<(E2 + 7) / 8, 256>>>(ei_on, E2, p_proj_m, LD_M,
                                        p_proj_op + 768, LD_OP, 768,
                                        p_rel + 16, p_dm, p_am);
    // type 3 (hosts, m->op): k seg 256 of machine row, v seg 512 (vofs 256)
    k_edge_fused<<<(E3 + 7) / 8, 256>>>(ei_ho, E3, p_proj_op, LD_OP,
                                        p_proj_m + 256, LD_M, 256,
                                        p_rel + 24, p_dop + 2 * N_OP * HH, p_a3);

    // finalize: softmax division + type sum + GELU
    k_final_op<<<(N_OP * DD + 255) / 256, 256>>>();
    k_final_m<<<(N_M * DD + 255) / 256, 256>>>();

    // final GEMMs with fused sigmoid-gated skip
    k_gemm_tf32<<<dim3(DD / 128, (N_OP + 127) / 128), 256>>>(
        p_oop, Wa, ba, out, N_OP, DD, DD, p_x0, skip, 0);
    k_gemm_tf32<<<dim3(DD / 128, (N_M + 127) / 128), 256>>>(
        p_om, Wa + 65536, ba + 256, out + (size_t)N_OP * DD, N_M, DD, DD, x_m, skip, 1);
}

// round 7
// speedup vs baseline: 3.0776x; 1.0554x over previous
#include <cuda_runtime.h>
#include <cuda_bf16.h>
#include <math.h>

#define N_OP 20000
#define N_M  500
#define NE   200000
#define DD   256
#define HH   8

#define LD_OP 1792   // [q | ka0 | ka1 | ka2 | va0 | va1 | va2]
#define LD_M  768    // [q | ka3 | va3]

// ---------------- scratch ----------------
__device__ float g_x0[N_OP * DD];
__device__ __nv_bfloat16 g_proj_op[(size_t)N_OP * LD_OP];
__device__ __nv_bfloat16 g_proj_m[N_M * LD_M];
__device__ float g_wop[LD_OP * DD];
__device__ float g_bop[LD_OP];
__device__ float g_wm[LD_M * DD];
__device__ float g_bm[LD_M];
__device__ float g_denom_op[3 * N_OP * HH];   // type slots 0,1,3
__device__ float g_denom_m[N_M * HH];
__device__ float g_acc0[N_OP * DD];           // unnormalized per-type sums
__device__ float g_acc1[N_OP * DD];
__device__ float g_acc3[N_OP * DD];
__device__ float g_accm[N_M * DD];
__device__ float g_out_op[N_OP * DD];
__device__ float g_out_m[N_M * DD];
__device__ float g_tstat[300];                // [G 256 | a 16 | h 16 | c0 | c1]
__device__ float g_tacc[N_OP * 20];           // [rs*temb 16 | sum_rs | sum_rs_mu | cnt | pad]

__device__ __forceinline__ void red_add_v4(float* p, float4 v) {
    asm volatile("red.global.add.v4.f32 [%0], {%1,%2,%3,%4};"
                 :: "l"(p), "f"(v.x), "f"(v.y), "f"(v.z), "f"(v.w) : "memory");
}

__device__ __forceinline__ unsigned f2tf32(float f) {
    unsigned u; asm("cvt.rna.tf32.f32 %0, %1;" : "=r"(u) : "f"(f)); return u;
}

__device__ __forceinline__ void mma_tf32(float* c, unsigned a0, unsigned a1,
                                         unsigned a2, unsigned a3,
                                         unsigned b0, unsigned b1) {
    asm volatile("mma.sync.aligned.m16n8k8.row.col.f32.tf32.tf32.f32 "
                 "{%0,%1,%2,%3}, {%4,%5,%6,%7}, {%8,%9}, {%0,%1,%2,%3};"
                 : "+f"(c[0]), "+f"(c[1]), "+f"(c[2]), "+f"(c[3])
                 : "r"(a0), "r"(a1), "r"(a2), "r"(a3), "r"(b0), "r"(b1));
}

// unpack 8 bf16 (one uint4) into 8 floats
__device__ __forceinline__ void bf8_to_f(const uint4 u, float* f) {
    float2 a = __bfloat1622float2(*(const __nv_bfloat162*)&u.x);
    float2 b = __bfloat1622float2(*(const __nv_bfloat162*)&u.y);
    float2 c = __bfloat1622float2(*(const __nv_bfloat162*)&u.z);
    float2 d = __bfloat1622float2(*(const __nv_bfloat162*)&u.w);
    f[0] = a.x; f[1] = a.y; f[2] = b.x; f[3] = b.y;
    f[4] = c.x; f[5] = c.y; f[6] = d.x; f[7] = d.y;
}

// ---------------- init / zero ----------------
__global__ void k_init(const float* __restrict__ x_op) {
    int i = blockIdx.x * blockDim.x + threadIdx.x;
    if (i < N_OP * DD / 4) ((float4*)g_x0)[i] = ((const float4*)x_op)[i];
}

__global__ void k_zero() {
    int i = blockIdx.x * blockDim.x + threadIdx.x;
    float4 z = make_float4(0.f, 0.f, 0.f, 0.f);
    if (i < N_OP * DD / 4) {
        ((float4*)g_acc0)[i] = z;
        ((float4*)g_acc1)[i] = z;
        ((float4*)g_acc3)[i] = z;
    }
    if (i < N_M * DD / 4) ((float4*)g_accm)[i] = z;
    if (i < 3 * N_OP * HH / 4) ((float4*)g_denom_op)[i] = z;
    if (i < N_M * HH / 4) ((float4*)g_denom_m)[i] = z;
    if (i < N_OP * 20 / 4) ((float4*)g_tacc)[i] = z;
}

// ---------------- weight stacking ----------------
__global__ void k_wstack(const float* __restrict__ Wk, const float* __restrict__ bk,
                         const float* __restrict__ Wq, const float* __restrict__ bq,
                         const float* __restrict__ Wv, const float* __restrict__ bv,
                         const float* __restrict__ a_rel, const float* __restrict__ m_rel) {
    int row = blockIdx.x;
    int in = threadIdx.x;
    float* wdst; float* bdst; int t;
    if (row < LD_OP) { wdst = g_wop; bdst = g_bop; t = 0; }
    else             { row -= LD_OP; wdst = g_wm; bdst = g_bm; t = 1; }
    int seg = row >> 8, o = row & 255;
    if (seg == 0) {
        wdst[row * DD + in] = Wq[t * 65536 + o * DD + in];
        if (in == 0) bdst[row] = bq[t * DD + o];
        return;
    }
    const float* rel; const float* Wb; const float* bb; int e;
    if (t == 0) {
        if (seg <= 3) { e = seg - 1; rel = a_rel; Wb = Wk; bb = bk; }
        else          { e = seg - 4; rel = m_rel; Wb = Wv; bb = bv; }
    } else {
        e = 3;
        if (seg == 1) { rel = a_rel; Wb = Wk; bb = bk; }
        else          { rel = m_rel; Wb = Wv; bb = bv; }
    }
    int h = o >> 5, f = o & 31;
    const float* rp = rel + ((e * 8 + h) * 32) * 32 + f;
    const float* W = Wb + t * 65536 + (h * 32) * DD;
    float acc = 0.f;
#pragma unroll 8
    for (int d = 0; d < 32; d++) acc += rp[d * 32] * W[d * DD + in];
    wdst[row * DD + in] = acc;
    if (in == 0) {
        float bacc = 0.f;
        const float* b = bb + t * DD + h * 32;
        for (int d = 0; d < 32; d++) bacc += rp[d * 32] * b[d];
        bdst[row] = bacc;
    }
}

// ---------------- temporal stats precompute: warp per Gram entry ----------------
__global__ void k_tprep(const float* __restrict__ Wt, const float* __restrict__ bt) {
    int b = blockIdx.x, t = threadIdx.x;
    if (b < 32) {
        int w = t >> 5, lane = t & 31;
        int idx = b * 8 + w;
        int c = idx >> 4, d = idx & 15;
        float acc = 0.f;
        for (int i = lane; i < 256; i += 32) acc += Wt[i * 16 + c] * Wt[i * 16 + d];
#pragma unroll
        for (int o = 16; o; o >>= 1) acc += __shfl_xor_sync(0xffffffffu, acc, o);
        if (lane == 0) g_tstat[idx] = acc * (1.f / 256.f);
    } else {
        if (t < 16) {
            float a = 0.f, h = 0.f;
            for (int i = 0; i < 256; i++) {
                float w = Wt[i * 16 + t];
                a += w; h += w * bt[i];
            }
            g_tstat[256 + t] = a * (1.f / 256.f);
            g_tstat[272 + t] = h * (1.f / 256.f);
        } else if (t == 16) {
            float c0 = 0.f, c1 = 0.f;
            for (int i = 0; i < 256; i++) { c0 += bt[i]; c1 += bt[i] * bt[i]; }
            g_tstat[288] = c0 * (1.f / 256.f);
            g_tstat[289] = c1 * (1.f / 256.f);
        }
    }
}

// ---------------- temporal edge pass: one thread per edge, 20-float moment scatter ----
__global__ void k_temporal2(const float* __restrict__ dtp, const int* __restrict__ ei, int E) {
    __shared__ float sG[256], sa[16], sh2[16], sc[2];
    int t = threadIdx.x;
    if (t < 256) sG[t] = g_tstat[t];
    if (t < 16) { sa[t] = g_tstat[256 + t]; sh2[t] = g_tstat[272 + t]; }
    if (t < 2) sc[t] = g_tstat[288 + t];
    __syncthreads();
    int e = blockIdx.x * blockDim.x + t;
    if (e >= E) return;
    float dt = dtp[e];
    float temb[16];
#pragma unroll
    for (int j = 0; j < 8; j++) {
        float s, c;
        sincosf(dt * exp2f(-1.2457230355827609f * (float)j), &s, &c);
        temb[2 * j] = s; temb[2 * j + 1] = c;
    }
    float mu = sc[0], hs = 0.f, q = 0.f;
#pragma unroll
    for (int c = 0; c < 16; c++) {
        mu += sa[c] * temb[c];
        hs += sh2[c] * temb[c];
        float r = 0.f;
#pragma unroll
        for (int d = 0; d < 16; d++) r += sG[c * 16 + d] * temb[d];
        q += r * temb[c];
    }
    float var = q + 2.f * hs + sc[1] - mu * mu;
    float rs = rsqrtf(var + 1e-5f);
    int src = ei[e];
    float* acc = g_tacc + (size_t)src * 20;
    red_add_v4(acc + 0,  make_float4(rs * temb[0],  rs * temb[1],  rs * temb[2],  rs * temb[3]));
    red_add_v4(acc + 4,  make_float4(rs * temb[4],  rs * temb[5],  rs * temb[6],  rs * temb[7]));
    red_add_v4(acc + 8,  make_float4(rs * temb[8],  rs * temb[9],  rs * temb[10], rs * temb[11]));
    red_add_v4(acc + 12, make_float4(rs * temb[12], rs * temb[13], rs * temb[14], rs * temb[15]));
    red_add_v4(acc + 16, make_float4(rs, rs * mu, 1.f, 0.f));
}

// ---------------- temporal finalize: x0 += g*(Wt@s16 + sr*bt - srm) + cnt*b ---------
__global__ void k_tfinal(const float* __restrict__ Wt, const float* __restrict__ bt,
                         const float* __restrict__ lng, const float* __restrict__ lnb) {
    __shared__ float s[20];
    int n = blockIdx.x, t = threadIdx.x;
    if (t < 20) s[t] = g_tacc[(size_t)n * 20 + t];
    __syncthreads();
    float cnt = s[18];
    if (cnt == 0.f) return;
    float sr = s[16], srm = s[17];
    const float4* wr = (const float4*)(Wt + t * 16);
    float4 w0 = wr[0], w1 = wr[1], w2 = wr[2], w3 = wr[3];
    float acc = w0.x * s[0] + w0.y * s[1] + w0.z * s[2] + w0.w * s[3]
              + w1.x * s[4] + w1.y * s[5] + w1.z * s[6] + w1.w * s[7]
              + w2.x * s[8] + w2.y * s[9] + w2.z * s[10] + w2.w * s[11]
              + w3.x * s[12] + w3.y * s[13] + w3.z * s[14] + w3.w * s[15];
    float y = lng[t] * (acc + sr * bt[t] - srm) + cnt * lnb[t];
    g_x0[(size_t)n * DD + t] += y;
}

// ---------------- tf32 tensor-core GEMM: C = A[M,256] @ W[N,256]^T + bias ----------
// outBF: write bf16 output (attention projections); else fp32 (+ optional gated skip).
__global__ void __launch_bounds__(256, 2)
k_gemm_tf32(const float* __restrict__ A, const float* __restrict__ W,
            const float* __restrict__ bias, void* __restrict__ C,
            int M, int lda, int ldc,
            const float* __restrict__ skipX, const float* __restrict__ skipP,
            int skipIdx, int outBF) {
    __shared__ unsigned sA[128][36];
    __shared__ unsigned sW[128][36];
    int tid = threadIdx.x;
    int lane = tid & 31, wid = tid >> 5;
    int gID = lane >> 2, tig = lane & 3;
    int mw = (wid >> 2) * 64, nw = (wid & 3) * 32;
    int m0 = blockIdx.y * 128, n0 = blockIdx.x * 128;
    int lr = tid >> 1;
    int lc0 = (tid & 1) * 16;
    float acc[4][4][4];
#pragma unroll
    for (int i = 0; i < 4; i++)
#pragma unroll
        for (int j = 0; j < 4; j++)
#pragma unroll
            for (int r = 0; r < 4; r++) acc[i][j][r] = 0.f;

    for (int k0 = 0; k0 < 256; k0 += 32) {
        int gm = m0 + lr;
#pragma unroll
        for (int j = 0; j < 4; j++) {
            float4 v = make_float4(0.f, 0.f, 0.f, 0.f);
            if (gm < M) v = *(const float4*)&A[(size_t)gm * lda + k0 + lc0 + j * 4];
            sA[lr][lc0 + 4 * j + 0] = f2tf32(v.x);
            sA[lr][lc0 + 4 * j + 1] = f2tf32(v.y);
            sA[lr][lc0 + 4 * j + 2] = f2tf32(v.z);
            sA[lr][lc0 + 4 * j + 3] = f2tf32(v.w);
        }
#pragma unroll
        for (int j = 0; j < 4; j++) {
            float4 v = *(const float4*)&W[(size_t)(n0 + lr) * 256 + k0 + lc0 + j * 4];
            sW[lr][lc0 + 4 * j + 0] = f2tf32(v.x);
            sW[lr][lc0 + 4 * j + 1] = f2tf32(v.y);
            sW[lr][lc0 + 4 * j + 2] = f2tf32(v.z);
            sW[lr][lc0 + 4 * j + 3] = f2tf32(v.w);
        }
        __syncthreads();
#pragma unroll
        for (int kk = 0; kk < 32; kk += 8) {
            unsigned bfr[4][2];
#pragma unroll
            for (int nt = 0; nt < 4; nt++) {
                int n = nw + nt * 8 + gID;
                bfr[nt][0] = sW[n][kk + tig];
                bfr[nt][1] = sW[n][kk + tig + 4];
            }
#pragma unroll
            for (int mt = 0; mt < 4; mt++) {
                int m = mw + mt * 16 + gID;
                unsigned a0 = sA[m][kk + tig];
                unsigned a1 = sA[m + 8][kk + tig];
                unsigned a2 = sA[m][kk + tig + 4];
                unsigned a3 = sA[m + 8][kk + tig + 4];
#pragma unroll
                for (int nt = 0; nt < 4; nt++)
                    mma_tf32(acc[mt][nt], a0, a1, a2, a3, bfr[nt][0], bfr[nt][1]);
            }
        }
        __syncthreads();
    }

    bool hs = (skipX != nullptr);
    float sa = 0.f, sb2 = 0.f;
    if (hs) { float s = skipP[skipIdx]; sa = 1.f / (1.f + __expf(-s)); sb2 = 1.f - sa; }
#pragma unroll
    for (int mt = 0; mt < 4; mt++) {
#pragma unroll
        for (int half = 0; half < 2; half++) {
            int m = m0 + mw + mt * 16 + gID + half * 8;
            if (m < M) {
#pragma unroll
                for (int nt = 0; nt < 4; nt++) {
                    int n = n0 + nw + nt * 8 + tig * 2;
                    float v0 = acc[mt][nt][half * 2 + 0] + bias[n];
                    float v1 = acc[mt][nt][half * 2 + 1] + bias[n + 1];
                    if (hs) {
                        v0 = sa * v0 + sb2 * skipX[(size_t)m * DD + n];
                        v1 = sa * v1 + sb2 * skipX[(size_t)m * DD + n + 1];
                    }
                    if (outBF) {
                        __nv_bfloat162* cp = (__nv_bfloat162*)((__nv_bfloat16*)C + (size_t)m * ldc + n);
                        *cp = __floats2bfloat162_rn(v0, v1);
                    } else {
                        *(float2*)((float*)C + (size_t)m * ldc + n) = make_float2(v0, v1);
                    }
                }
            }
        }
    }
}

// ---------------- fused edge pass (bf16 gathers): alpha -> exp -> scatter + denom ----
// one warp per edge.  kvb row holds both k (at 0) and v (at vofs, in elements).
__global__ void k_edge_fused(const int* __restrict__ ei, int E,
                             const __nv_bfloat16* __restrict__ qb, int qld,
                             const __nv_bfloat16* __restrict__ kvb, int kvld, int vofs,
                             const float* __restrict__ prel,
                             float* __restrict__ denom, float* __restrict__ out) {
    int w = (blockIdx.x * blockDim.x + threadIdx.x) >> 5;
    if (w >= E) return;
    int lane = threadIdx.x & 31;
    int src = ei[w], dst = ei[E + w];
    uint4 qu = *((const uint4*)(qb + (size_t)dst * qld) + lane);
    uint4 ku = *((const uint4*)(kvb + (size_t)src * kvld) + lane);
    uint4 vu = *((const uint4*)(kvb + (size_t)src * kvld + vofs) + lane);
    float qf[8], kf[8], vf[8];
    bf8_to_f(qu, qf); bf8_to_f(ku, kf); bf8_to_f(vu, vf);
    float p = 0.f;
#pragma unroll
    for (int i = 0; i < 8; i++) p += qf[i] * kf[i];
    p += __shfl_xor_sync(0xffffffffu, p, 1);
    p += __shfl_xor_sync(0xffffffffu, p, 2);
    float a = __shfl_sync(0xffffffffu, p, (lane * 4) & 31);   // lane h<8: head h dot
    float ex = 0.f;
    if (lane < 8) ex = __expf(a * prel[lane] * 0.17677669529663687f);
    float wh = __shfl_sync(0xffffffffu, ex, lane >> 2);       // per-lane head weight
    float* o = out + (size_t)dst * DD + lane * 8;
    red_add_v4(o, make_float4(vf[0] * wh, vf[1] * wh, vf[2] * wh, vf[3] * wh));
    red_add_v4(o + 4, make_float4(vf[4] * wh, vf[5] * wh, vf[6] * wh, vf[7] * wh));
    if (lane < 8) atomicAdd(&denom[(size_t)dst * 8 + lane], ex);
}

// ---------------- finalize: divide by denoms, sum types, exact GELU ----------------
__global__ void k_final_op() {
    int i = blockIdx.x * blockDim.x + threadIdx.x;
    if (i >= N_OP * DD) return;
    int n = i >> 8, h = (i & 255) >> 5;
    float val = 0.f, d;
    d = g_denom_op[n * 8 + h];                 if (d > 0.f) val += g_acc0[i] / d;
    d = g_denom_op[N_OP * 8 + n * 8 + h];      if (d > 0.f) val += g_acc1[i] / d;
    d = g_denom_op[2 * N_OP * 8 + n * 8 + h];  if (d > 0.f) val += g_acc3[i] / d;
    g_out_op[i] = 0.5f * val * (1.f + erff(val * 0.70710678118654752f));
}

__global__ void k_final_m() {
    int i = blockIdx.x * blockDim.x + threadIdx.x;
    if (i >= N_M * DD) return;
    int n = i >> 8, h = (i & 255) >> 5;
    float val = 0.f;
    float d = g_denom_m[n * 8 + h];
    if (d > 0.f) val = g_accm[i] / d;
    g_out_m[i] = 0.5f * val * (1.f + erff(val * 0.70710678118654752f));
}

// ---------------- launch ----------------
extern "C" void kernel_launch(void* const* d_in, const int* in_sizes, int n_in,
                              void* d_out, int out_size) {
    const float* x_op = (const float*)d_in[0];
    const float* x_m  = (const float*)d_in[1];
    const float* dtp  = (const float*)d_in[2];
    const int* ei_mp  = (const int*)d_in[3];
    const int* ei_pr  = (const int*)d_in[4];
    const int* ei_on  = (const int*)d_in[5];
    const int* ei_ho  = (const int*)d_in[6];
    const float* Wt   = (const float*)d_in[7];
    const float* bt   = (const float*)d_in[8];
    const float* lng  = (const float*)d_in[9];
    const float* lnb  = (const float*)d_in[10];
    const float* Wk   = (const float*)d_in[11];
    const float* bk   = (const float*)d_in[12];
    const float* Wq   = (const float*)d_in[13];
    const float* bq   = (const float*)d_in[14];
    const float* Wv   = (const float*)d_in[15];
    const float* bv   = (const float*)d_in[16];
    const float* Wa   = (const float*)d_in[17];
    const float* ba   = (const float*)d_in[18];
    const float* skip = (const float*)d_in[19];
    const float* a_rel = (const float*)d_in[20];
    const float* m_rel = (const float*)d_in[21];
    const float* p_rel = (const float*)d_in[22];
    float* out = (float*)d_out;

    float *p_x0, *p_wop, *p_bop, *p_wm, *p_bm;
    float *p_dop, *p_dm, *p_oop, *p_om, *p_a0, *p_a1, *p_a3, *p_am;
    __nv_bfloat16 *p_pop, *p_pm;
    cudaGetSymbolAddress((void**)&p_x0, g_x0);
    cudaGetSymbolAddress((void**)&p_pop, g_proj_op);
    cudaGetSymbolAddress((void**)&p_pm, g_proj_m);
    cudaGetSymbolAddress((void**)&p_wop, g_wop);
    cudaGetSymbolAddress((void**)&p_bop, g_bop);
    cudaGetSymbolAddress((void**)&p_wm, g_wm);
    cudaGetSymbolAddress((void**)&p_bm, g_bm);
    cudaGetSymbolAddress((void**)&p_dop, g_denom_op);
    cudaGetSymbolAddress((void**)&p_dm, g_denom_m);
    cudaGetSymbolAddress((void**)&p_oop, g_out_op);
    cudaGetSymbolAddress((void**)&p_om, g_out_m);
    cudaGetSymbolAddress((void**)&p_a0, g_acc0);
    cudaGetSymbolAddress((void**)&p_a1, g_acc1);
    cudaGetSymbolAddress((void**)&p_a3, g_acc3);
    cudaGetSymbolAddress((void**)&p_am, g_accm);

    int E0 = in_sizes[3] / 2, E1 = in_sizes[4] / 2, E2 = in_sizes[5] / 2, E3 = in_sizes[6] / 2;

    k_init<<<(N_OP * DD / 4 + 255) / 256, 256>>>(x_op);
    k_zero<<<(N_OP * DD / 4 + 255) / 256, 256>>>();
    k_wstack<<<LD_OP + LD_M, 256>>>(Wk, bk, Wq, bq, Wv, bv, a_rel, m_rel);
    k_tprep<<<33, 256>>>(Wt, bt);
    k_temporal2<<<(E0 + 255) / 256, 256>>>(dtp, ei_mp, E0);
    k_tfinal<<<N_OP, 256>>>(Wt, bt, lng, lnb);

    // stacked projections (tf32 tensor cores, bf16 output)
    k_gemm_tf32<<<dim3(LD_OP / 128, (N_OP + 127) / 128), 256>>>(
        p_x0, p_wop, p_bop, p_pop, N_OP, DD, LD_OP, nullptr, nullptr, 0, 1);
    k_gemm_tf32<<<dim3(LD_M / 128, (N_M + 127) / 128), 256>>>(
        x_m, p_wm, p_bm, p_pm, N_M, DD, LD_M, nullptr, nullptr, 0, 1);

    // fused edge passes: unnormalized scatter + denominators (bf16 gathers)
    // type 0 (mp, op->op):   k seg 256,  v seg 1024 (vofs 768)
    k_edge_fused<<<(E0 + 7) / 8, 256>>>(ei_mp, E0, p_pop, LD_OP,
                                        p_pop + 256, LD_OP, 768,
                                        p_rel + 0, p_dop, p_a0);
    // type 1 (prec, op->op): k seg 512,  v seg 1280
    k_edge_fused<<<(E1 + 7) / 8, 256>>>(ei_pr, E1, p_pop, LD_OP,
                                        p_pop + 512, LD_OP, 768,
                                        p_rel + 8, p_dop + N_OP * HH, p_a1);
    // type 2 (on, op->m):    k seg 768,  v seg 1536;  q from machines
    k_edge_fused<<<(E2 + 7) / 8, 256>>>(ei_on, E2, p_pm, LD_M,
                                        p_pop + 768, LD_OP, 768,
                                        p_rel + 16, p_dm, p_am);
    // type 3 (hosts, m->op): k seg 256 of machine row, v seg 512 (vofs 256)
    k_edge_fused<<<(E3 + 7) / 8, 256>>>(ei_ho, E3, p_pop, LD_OP,
                                        p_pm + 256, LD_M, 256,
                                        p_rel + 24, p_dop + 2 * N_OP * HH, p_a3);

    // finalize: softmax division + type sum + GELU
    k_final_op<<<(N_OP * DD + 255) / 256, 256>>>();
    k_final_m<<<(N_M * DD + 255) / 256, 256>>>();

    // final GEMMs with fused sigmoid-gated skip (fp32 output to d_out)
    k_gemm_tf32<<<dim3(DD / 128, (N_OP + 127) / 128), 256>>>(
        p_oop, Wa, ba, out, N_OP, DD, DD, p_x0, skip, 0, 0);
    k_gemm_tf32<<<dim3(DD / 128, (N_M + 127) / 128), 256>>>(
        p_om, Wa + 65536, ba + 256, out + (size_t)N_OP * DD, N_M, DD, DD, x_m, skip, 1, 0);
}

// round 8
// speedup vs baseline: 3.1932x; 1.0376x over previous
#include <cuda_runtime.h>
#include <cuda_bf16.h>
#include <math.h>

#define N_OP 20000
#define N_M  500
#define NE   200000
#define DD   256
#define HH   8

#define LD_OP 1792   // [q | ka0 | ka1 | ka2 | va0 | va1 | va2]
#define LD_M  768    // [q | ka3 | va3]

// ---------------- scratch ----------------
__device__ float g_x0[N_OP * DD];
__device__ __nv_bfloat16 g_proj_op[(size_t)N_OP * LD_OP];
__device__ __nv_bfloat16 g_proj_m[N_M * LD_M];
__device__ float g_wop[LD_OP * DD];
__device__ float g_bop[LD_OP];
__device__ float g_wm[LD_M * DD];
__device__ float g_bm[LD_M];
__device__ float g_denom_op[3 * N_OP * HH];   // type slots 0,1,3
__device__ float g_denom_m[N_M * HH];
__device__ float g_acc0[N_OP * DD];           // unnormalized per-type sums
__device__ float g_acc1[N_OP * DD];
__device__ float g_acc3[N_OP * DD];
__device__ float g_accm[N_M * DD];
__device__ float g_tstat[300];                // [G 256 | a 16 | h 16 | c0 | c1]
__device__ float g_tacc[N_OP * 20];           // [rs*temb 16 | sum_rs | sum_rs_mu | cnt | pad]

struct GemmCfg {
    const float* A; const float* W; const float* bias; void* C;
    int M, lda, ldc, gx, gy;
    const float* skipX; int skipIdx; int outBF; int amode;  // amode 0=plain,1=op-acc,2=m-acc
};

struct EdgeCfg {
    const int* ei; int E;
    const __nv_bfloat16* qb; int qld;
    const __nv_bfloat16* kvb; int kvld; int vofs;
    float* denom; float* out;
};

__device__ __forceinline__ void red_add_v4(float* p, float4 v) {
    asm volatile("red.global.add.v4.f32 [%0], {%1,%2,%3,%4};"
                 :: "l"(p), "f"(v.x), "f"(v.y), "f"(v.z), "f"(v.w) : "memory");
}

__device__ __forceinline__ unsigned f2tf32(float f) {
    unsigned u; asm("cvt.rna.tf32.f32 %0, %1;" : "=r"(u) : "f"(f)); return u;
}

__device__ __forceinline__ void mma_tf32(float* c, unsigned a0, unsigned a1,
                                         unsigned a2, unsigned a3,
                                         unsigned b0, unsigned b1) {
    asm volatile("mma.sync.aligned.m16n8k8.row.col.f32.tf32.tf32.f32 "
                 "{%0,%1,%2,%3}, {%4,%5,%6,%7}, {%8,%9}, {%0,%1,%2,%3};"
                 : "+f"(c[0]), "+f"(c[1]), "+f"(c[2]), "+f"(c[3])
                 : "r"(a0), "r"(a1), "r"(a2), "r"(a3), "r"(b0), "r"(b1));
}

__device__ __forceinline__ void bf8_to_f(const uint4 u, float* f) {
    float2 a = __bfloat1622float2(*(const __nv_bfloat162*)&u.x);
    float2 b = __bfloat1622float2(*(const __nv_bfloat162*)&u.y);
    float2 c = __bfloat1622float2(*(const __nv_bfloat162*)&u.z);
    float2 d = __bfloat1622float2(*(const __nv_bfloat162*)&u.w);
    f[0] = a.x; f[1] = a.y; f[2] = b.x; f[3] = b.y;
    f[4] = c.x; f[5] = c.y; f[6] = d.x; f[7] = d.y;
}

__device__ __forceinline__ float gelu1(float x) {
    return 0.5f * x * (1.f + erff(x * 0.70710678118654752f));
}

// ---------------- init + zero (merged) ----------------
__global__ void k_initzero(const float* __restrict__ x_op) {
    int i = blockIdx.x * blockDim.x + threadIdx.x;
    float4 z = make_float4(0.f, 0.f, 0.f, 0.f);
    if (i < N_OP * DD / 4) {
        ((float4*)g_x0)[i] = ((const float4*)x_op)[i];
        ((float4*)g_acc0)[i] = z;
        ((float4*)g_acc1)[i] = z;
        ((float4*)g_acc3)[i] = z;
    }
    if (i < N_M * DD / 4) ((float4*)g_accm)[i] = z;
    if (i < 3 * N_OP * HH / 4) ((float4*)g_denom_op)[i] = z;
    if (i < N_M * HH / 4) ((float4*)g_denom_m)[i] = z;
    if (i < N_OP * 20 / 4) ((float4*)g_tacc)[i] = z;
}

// ---------------- weight stacking ----------------
__global__ void k_wstack(const float* __restrict__ Wk, const float* __restrict__ bk,
                         const float* __restrict__ Wq, const float* __restrict__ bq,
                         const float* __restrict__ Wv, const float* __restrict__ bv,
                         const float* __restrict__ a_rel, const float* __restrict__ m_rel) {
    int row = blockIdx.x;
    int in = threadIdx.x;
    float* wdst; float* bdst; int t;
    if (row < LD_OP) { wdst = g_wop; bdst = g_bop; t = 0; }
    else             { row -= LD_OP; wdst = g_wm; bdst = g_bm; t = 1; }
    int seg = row >> 8, o = row & 255;
    if (seg == 0) {
        wdst[row * DD + in] = Wq[t * 65536 + o * DD + in];
        if (in == 0) bdst[row] = bq[t * DD + o];
        return;
    }
    const float* rel; const float* Wb; const float* bb; int e;
    if (t == 0) {
        if (seg <= 3) { e = seg - 1; rel = a_rel; Wb = Wk; bb = bk; }
        else          { e = seg - 4; rel = m_rel; Wb = Wv; bb = bv; }
    } else {
        e = 3;
        if (seg == 1) { rel = a_rel; Wb = Wk; bb = bk; }
        else          { rel = m_rel; Wb = Wv; bb = bv; }
    }
    int h = o >> 5, f = o & 31;
    const float* rp = rel + ((e * 8 + h) * 32) * 32 + f;
    const float* W = Wb + t * 65536 + (h * 32) * DD;
    float acc = 0.f;
#pragma unroll 8
    for (int d = 0; d < 32; d++) acc += rp[d * 32] * W[d * DD + in];
    wdst[row * DD + in] = acc;
    if (in == 0) {
        float bacc = 0.f;
        const float* b = bb + t * DD + h * 32;
        for (int d = 0; d < 32; d++) bacc += rp[d * 32] * b[d];
        bdst[row] = bacc;
    }
}

// ---------------- temporal stats precompute: warp per Gram entry ----------------
__global__ void k_tprep(const float* __restrict__ Wt, const float* __restrict__ bt) {
    int b = blockIdx.x, t = threadIdx.x;
    if (b < 32) {
        int w = t >> 5, lane = t & 31;
        int idx = b * 8 + w;
        int c = idx >> 4, d = idx & 15;
        float acc = 0.f;
        for (int i = lane; i < 256; i += 32) acc += Wt[i * 16 + c] * Wt[i * 16 + d];
#pragma unroll
        for (int o = 16; o; o >>= 1) acc += __shfl_xor_sync(0xffffffffu, acc, o);
        if (lane == 0) g_tstat[idx] = acc * (1.f / 256.f);
    } else {
        if (t < 16) {
            float a = 0.f, h = 0.f;
            for (int i = 0; i < 256; i++) {
                float w = Wt[i * 16 + t];
                a += w; h += w * bt[i];
            }
            g_tstat[256 + t] = a * (1.f / 256.f);
            g_tstat[272 + t] = h * (1.f / 256.f);
        } else if (t == 16) {
            float c0 = 0.f, c1 = 0.f;
            for (int i = 0; i < 256; i++) { c0 += bt[i]; c1 += bt[i] * bt[i]; }
            g_tstat[288] = c0 * (1.f / 256.f);
            g_tstat[289] = c1 * (1.f / 256.f);
        }
    }
}

// ---------------- temporal edge pass: one thread per edge, 20-float moment scatter ----
__global__ void k_temporal2(const float* __restrict__ dtp, const int* __restrict__ ei, int E) {
    __shared__ float sG[256], sa[16], sh2[16], sc[2];
    int t = threadIdx.x;
    if (t < 256) sG[t] = g_tstat[t];
    if (t < 16) { sa[t] = g_tstat[256 + t]; sh2[t] = g_tstat[272 + t]; }
    if (t < 2) sc[t] = g_tstat[288 + t];
    __syncthreads();
    int e = blockIdx.x * blockDim.x + t;
    if (e >= E) return;
    float dt = dtp[e];
    float temb[16];
#pragma unroll
    for (int j = 0; j < 8; j++) {
        float s, c;
        sincosf(dt * exp2f(-1.2457230355827609f * (float)j), &s, &c);
        temb[2 * j] = s; temb[2 * j + 1] = c;
    }
    float mu = sc[0], hs = 0.f, q = 0.f;
#pragma unroll
    for (int c = 0; c < 16; c++) {
        mu += sa[c] * temb[c];
        hs += sh2[c] * temb[c];
        float r = 0.f;
#pragma unroll
        for (int d = 0; d < 16; d++) r += sG[c * 16 + d] * temb[d];
        q += r * temb[c];
    }
    float var = q + 2.f * hs + sc[1] - mu * mu;
    float rs = rsqrtf(var + 1e-5f);
    int src = ei[e];
    float* acc = g_tacc + (size_t)src * 20;
    red_add_v4(acc + 0,  make_float4(rs * temb[0],  rs * temb[1],  rs * temb[2],  rs * temb[3]));
    red_add_v4(acc + 4,  make_float4(rs * temb[4],  rs * temb[5],  rs * temb[6],  rs * temb[7]));
    red_add_v4(acc + 8,  make_float4(rs * temb[8],  rs * temb[9],  rs * temb[10], rs * temb[11]));
    red_add_v4(acc + 12, make_float4(rs * temb[12], rs * temb[13], rs * temb[14], rs * temb[15]));
    red_add_v4(acc + 16, make_float4(rs, rs * mu, 1.f, 0.f));
}

// ---------------- temporal finalize: x0 += g*(Wt@s16 + sr*bt - srm) + cnt*b ---------
__global__ void k_tfinal(const float* __restrict__ Wt, const float* __restrict__ bt,
                         const float* __restrict__ lng, const float* __restrict__ lnb) {
    __shared__ float s[20];
    int n = blockIdx.x, t = threadIdx.x;
    if (t < 20) s[t] = g_tacc[(size_t)n * 20 + t];
    __syncthreads();
    float cnt = s[18];
    if (cnt == 0.f) return;
    float sr = s[16], srm = s[17];
    const float4* wr = (const float4*)(Wt + t * 16);
    float4 w0 = wr[0], w1 = wr[1], w2 = wr[2], w3 = wr[3];
    float acc = w0.x * s[0] + w0.y * s[1] + w0.z * s[2] + w0.w * s[3]
              + w1.x * s[4] + w1.y * s[5] + w1.z * s[6] + w1.w * s[7]
              + w2.x * s[8] + w2.y * s[9] + w2.z * s[10] + w2.w * s[11]
              + w3.x * s[12] + w3.y * s[13] + w3.z * s[14] + w3.w * s[15];
    float y = lng[t] * (acc + sr * bt[t] - srm) + cnt * lnb[t];
    g_x0[(size_t)n * DD + t] += y;
}

// ---------------- tf32 tensor-core GEMM, two configs per launch (blockIdx.z) --------
// amode 0: A = cfg.A (plain fp32).  amode 1: A = sum_t acc_t/denom_t, GELU (op).
// amode 2: A = accm/denom_m, GELU (machine).
__global__ void __launch_bounds__(256, 2)
k_gemm2(GemmCfg c0, GemmCfg c1, const float* __restrict__ skipP) {
    GemmCfg c = blockIdx.z ? c1 : c0;
    if (blockIdx.x >= (unsigned)c.gx || blockIdx.y >= (unsigned)c.gy) return;
    __shared__ unsigned sA[128][36];
    __shared__ unsigned sW[128][36];
    int tid = threadIdx.x;
    int lane = tid & 31, wid = tid >> 5;
    int gID = lane >> 2, tig = lane & 3;
    int mw = (wid >> 2) * 64, nw = (wid & 3) * 32;
    int m0 = blockIdx.y * 128, n0 = blockIdx.x * 128;
    int lr = tid >> 1;
    int lc0 = (tid & 1) * 16;
    float acc[4][4][4];
#pragma unroll
    for (int i = 0; i < 4; i++)
#pragma unroll
        for (int j = 0; j < 4; j++)
#pragma unroll
            for (int r = 0; r < 4; r++) acc[i][j][r] = 0.f;

    for (int k0 = 0; k0 < 256; k0 += 32) {
        int gm = m0 + lr;
#pragma unroll
        for (int j = 0; j < 4; j++) {
            int col = k0 + lc0 + j * 4;
            float4 v = make_float4(0.f, 0.f, 0.f, 0.f);
            if (gm < c.M) {
                if (c.amode == 0) {
                    v = *(const float4*)&c.A[(size_t)gm * c.lda + col];
                } else if (c.amode == 1) {
                    int h = col >> 5;
                    float d0 = g_denom_op[gm * 8 + h];
                    float d1 = g_denom_op[N_OP * 8 + gm * 8 + h];
                    float d2 = g_denom_op[2 * N_OP * 8 + gm * 8 + h];
                    float i0 = d0 > 0.f ? 1.f / d0 : 0.f;
                    float i1 = d1 > 0.f ? 1.f / d1 : 0.f;
                    float i2 = d2 > 0.f ? 1.f / d2 : 0.f;
                    float4 a0 = *(const float4*)&g_acc0[gm * DD + col];
                    float4 a1 = *(const float4*)&g_acc1[gm * DD + col];
                    float4 a2 = *(const float4*)&g_acc3[gm * DD + col];
                    v.x = gelu1(a0.x * i0 + a1.x * i1 + a2.x * i2);
                    v.y = gelu1(a0.y * i0 + a1.y * i1 + a2.y * i2);
                    v.z = gelu1(a0.z * i0 + a1.z * i1 + a2.z * i2);
                    v.w = gelu1(a0.w * i0 + a1.w * i1 + a2.w * i2);
                } else {
                    int h = col >> 5;
                    float d = g_denom_m[gm * 8 + h];
                    float iv = d > 0.f ? 1.f / d : 0.f;
                    float4 a = *(const float4*)&g_accm[gm * DD + col];
                    v.x = gelu1(a.x * iv); v.y = gelu1(a.y * iv);
                    v.z = gelu1(a.z * iv); v.w = gelu1(a.w * iv);
                }
            }
            sA[lr][lc0 + 4 * j + 0] = f2tf32(v.x);
            sA[lr][lc0 + 4 * j + 1] = f2tf32(v.y);
            sA[lr][lc0 + 4 * j + 2] = f2tf32(v.z);
            sA[lr][lc0 + 4 * j + 3] = f2tf32(v.w);
        }
#pragma unroll
        for (int j = 0; j < 4; j++) {
            float4 v = *(const float4*)&c.W[(size_t)(n0 + lr) * 256 + k0 + lc0 + j * 4];
            sW[lr][lc0 + 4 * j + 0] = f2tf32(v.x);
            sW[lr][lc0 + 4 * j + 1] = f2tf32(v.y);
            sW[lr][lc0 + 4 * j + 2] = f2tf32(v.z);
            sW[lr][lc0 + 4 * j + 3] = f2tf32(v.w);
        }
        __syncthreads();
#pragma unroll
        for (int kk = 0; kk < 32; kk += 8) {
            unsigned bfr[4][2];
#pragma unroll
            for (int nt = 0; nt < 4; nt++) {
                int n = nw + nt * 8 + gID;
                bfr[nt][0] = sW[n][kk + tig];
                bfr[nt][1] = sW[n][kk + tig + 4];
            }
#pragma unroll
            for (int mt = 0; mt < 4; mt++) {
                int m = mw + mt * 16 + gID;
                unsigned a0 = sA[m][kk + tig];
                unsigned a1 = sA[m + 8][kk + tig];
                unsigned a2 = sA[m][kk + tig + 4];
                unsigned a3 = sA[m + 8][kk + tig + 4];
#pragma unroll
                for (int nt = 0; nt < 4; nt++)
                    mma_tf32(acc[mt][nt], a0, a1, a2, a3, bfr[nt][0], bfr[nt][1]);
            }
        }
        __syncthreads();
    }

    bool hs = (c.skipX != nullptr);
    float sa = 0.f, sb2 = 0.f;
    if (hs) { float s = skipP[c.skipIdx]; sa = 1.f / (1.f + __expf(-s)); sb2 = 1.f - sa; }
#pragma unroll
    for (int mt = 0; mt < 4; mt++) {
#pragma unroll
        for (int half = 0; half < 2; half++) {
            int m = m0 + mw + mt * 16 + gID + half * 8;
            if (m < c.M) {
#pragma unroll
                for (int nt = 0; nt < 4; nt++) {
                    int n = n0 + nw + nt * 8 + tig * 2;
                    float v0 = acc[mt][nt][half * 2 + 0] + c.bias[n];
                    float v1 = acc[mt][nt][half * 2 + 1] + c.bias[n + 1];
                    if (hs) {
                        v0 = sa * v0 + sb2 * c.skipX[(size_t)m * DD + n];
                        v1 = sa * v1 + sb2 * c.skipX[(size_t)m * DD + n + 1];
                    }
                    if (c.outBF) {
                        __nv_bfloat162* cp = (__nv_bfloat162*)((__nv_bfloat16*)c.C + (size_t)m * c.ldc + n);
                        *cp = __floats2bfloat162_rn(v0, v1);
                    } else {
                        *(float2*)((float*)c.C + (size_t)m * c.ldc + n) = make_float2(v0, v1);
                    }
                }
            }
        }
    }
}

// ---------------- merged fused edge pass: all 4 types in one launch ----------------
__global__ void k_edge_all(EdgeCfg e0, EdgeCfg e1, EdgeCfg e2, EdgeCfg e3,
                           const float* __restrict__ prel, int bpt) {
    int ty = blockIdx.x / bpt;
    EdgeCfg c = (ty == 0) ? e0 : (ty == 1) ? e1 : (ty == 2) ? e2 : e3;
    int w = (blockIdx.x - ty * bpt) * 8 + (threadIdx.x >> 5);
    if (w >= c.E) return;
    int lane = threadIdx.x & 31;
    int src = c.ei[w], dst = c.ei[c.E + w];
    uint4 qu = *((const uint4*)(c.qb + (size_t)dst * c.qld) + lane);
    uint4 ku = *((const uint4*)(c.kvb + (size_t)src * c.kvld) + lane);
    uint4 vu = *((const uint4*)(c.kvb + (size_t)src * c.kvld + c.vofs) + lane);
    float qf[8], kf[8], vf[8];
    bf8_to_f(qu, qf); bf8_to_f(ku, kf); bf8_to_f(vu, vf);
    float p = 0.f;
#pragma unroll
    for (int i = 0; i < 8; i++) p += qf[i] * kf[i];
    p += __shfl_xor_sync(0xffffffffu, p, 1);
    p += __shfl_xor_sync(0xffffffffu, p, 2);
    float a = __shfl_sync(0xffffffffu, p, (lane * 4) & 31);   // lane h<8: head h dot
    float ex = 0.f;
    if (lane < 8) ex = __expf(a * prel[ty * 8 + lane] * 0.17677669529663687f);
    float wh = __shfl_sync(0xffffffffu, ex, lane >> 2);       // per-lane head weight
    float* o = c.out + (size_t)dst * DD + lane * 8;
    red_add_v4(o, make_float4(vf[0] * wh, vf[1] * wh, vf[2] * wh, vf[3] * wh));
    red_add_v4(o + 4, make_float4(vf[4] * wh, vf[5] * wh, vf[6] * wh, vf[7] * wh));
    // denom: 2 v4 REDs from lanes 0,1 (heads 0-3 / 4-7)
    int base = (lane & 1) * 4;
    float d0 = __shfl_sync(0xffffffffu, ex, base + 0);
    float d1 = __shfl_sync(0xffffffffu, ex, base + 1);
    float d2 = __shfl_sync(0xffffffffu, ex, base + 2);
    float d3 = __shfl_sync(0xffffffffu, ex, base + 3);
    if (lane < 2)
        red_add_v4(c.denom + (size_t)dst * 8 + lane * 4, make_float4(d0, d1, d2, d3));
}

// ---------------- launch ----------------
extern "C" void kernel_launch(void* const* d_in, const int* in_sizes, int n_in,
                              void* d_out, int out_size) {
    const float* x_op = (const float*)d_in[0];
    const float* x_m  = (const float*)d_in[1];
    const float* dtp  = (const float*)d_in[2];
    const int* ei_mp  = (const int*)d_in[3];
    const int* ei_pr  = (const int*)d_in[4];
    const int* ei_on  = (const int*)d_in[5];
    const int* ei_ho  = (const int*)d_in[6];
    const float* Wt   = (const float*)d_in[7];
    const float* bt   = (const float*)d_in[8];
    const float* lng  = (const float*)d_in[9];
    const float* lnb  = (const float*)d_in[10];
    const float* Wk   = (const float*)d_in[11];
    const float* bk   = (const float*)d_in[12];
    const float* Wq   = (const float*)d_in[13];
    const float* bq   = (const float*)d_in[14];
    const float* Wv   = (const float*)d_in[15];
    const float* bv   = (const float*)d_in[16];
    const float* Wa   = (const float*)d_in[17];
    const float* ba   = (const float*)d_in[18];
    const float* skip = (const float*)d_in[19];
    const float* a_rel = (const float*)d_in[20];
    const float* m_rel = (const float*)d_in[21];
    const float* p_rel = (const float*)d_in[22];
    float* out = (float*)d_out;

    float *p_x0, *p_wop, *p_bop, *p_wm, *p_bm;
    float *p_dop, *p_dm, *p_a0, *p_a1, *p_a3, *p_am;
    __nv_bfloat16 *p_pop, *p_pm;
    cudaGetSymbolAddress((void**)&p_x0, g_x0);
    cudaGetSymbolAddress((void**)&p_pop, g_proj_op);
    cudaGetSymbolAddress((void**)&p_pm, g_proj_m);
    cudaGetSymbolAddress((void**)&p_wop, g_wop);
    cudaGetSymbolAddress((void**)&p_bop, g_bop);
    cudaGetSymbolAddress((void**)&p_wm, g_wm);
    cudaGetSymbolAddress((void**)&p_bm, g_bm);
    cudaGetSymbolAddress((void**)&p_dop, g_denom_op);
    cudaGetSymbolAddress((void**)&p_dm, g_denom_m);
    cudaGetSymbolAddress((void**)&p_a0, g_acc0);
    cudaGetSymbolAddress((void**)&p_a1, g_acc1);
    cudaGetSymbolAddress((void**)&p_a3, g_acc3);
    cudaGetSymbolAddress((void**)&p_am, g_accm);

    int E0 = in_sizes[3] / 2, E1 = in_sizes[4] / 2, E2 = in_sizes[5] / 2, E3 = in_sizes[6] / 2;

    k_initzero<<<(N_OP * DD / 4 + 255) / 256, 256>>>(x_op);
    k_wstack<<<LD_OP + LD_M, 256>>>(Wk, bk, Wq, bq, Wv, bv, a_rel, m_rel);
    k_tprep<<<33, 256>>>(Wt, bt);
    k_temporal2<<<(E0 + 255) / 256, 256>>>(dtp, ei_mp, E0);
    k_tfinal<<<N_OP, 256>>>(Wt, bt, lng, lnb);

    // stacked projections (op + machine in one launch, bf16 out)
    {
        GemmCfg cOp = {p_x0, p_wop, p_bop, p_pop, N_OP, DD, LD_OP,
                       LD_OP / 128, (N_OP + 127) / 128, nullptr, 0, 1, 0};
        GemmCfg cM  = {x_m, p_wm, p_bm, p_pm, N_M, DD, LD_M,
                       LD_M / 128, (N_M + 127) / 128, nullptr, 0, 1, 0};
        k_gemm2<<<dim3(LD_OP / 128, (N_OP + 127) / 128, 2), 256>>>(cOp, cM, nullptr);
    }

    // merged fused edge pass (all 4 types)
    {
        int Emax = E0;
        if (E1 > Emax) Emax = E1;
        if (E2 > Emax) Emax = E2;
        if (E3 > Emax) Emax = E3;
        int bpt = (Emax + 7) / 8;
        EdgeCfg e0 = {ei_mp, E0, p_pop, LD_OP, p_pop + 256, LD_OP, 768, p_dop, p_a0};
        EdgeCfg e1 = {ei_pr, E1, p_pop, LD_OP, p_pop + 512, LD_OP, 768, p_dop + N_OP * HH, p_a1};
        EdgeCfg e2 = {ei_on, E2, p_pm, LD_M, p_pop + 768, LD_OP, 768, p_dm, p_am};
        EdgeCfg e3 = {ei_ho, E3, p_pop, LD_OP, p_pm + 256, LD_M, 256, p_dop + 2 * N_OP * HH, p_a3};
        k_edge_all<<<4 * bpt, 256>>>(e0, e1, e2, e3, p_rel, bpt);
    }

    // final GEMMs (op + machine in one launch) with fused softmax-division + GELU +
    // sigmoid-gated skip, writing fp32 directly to d_out
    {
        GemmCfg cOp = {nullptr, Wa, ba, out, N_OP, DD, DD,
                       2, (N_OP + 127) / 128, p_x0, 0, 0, 1};
        GemmCfg cM  = {nullptr, Wa + 65536, ba + 256, out + (size_t)N_OP * DD, N_M, DD, DD,
                       2, (N_M + 127) / 128, x_m, 1, 0, 2};
        k_gemm2<<<dim3(2, (N_OP + 127) / 128, 2), 256>>>(cOp, cM, skip);
    }
}

// round 9
// speedup vs baseline: 3.8210x; 1.1966x over previous
#include <cuda_runtime.h>
#include <cuda_bf16.h>
#include <math.h>

#define N_OP 20000
#define N_M  500
#define NE   200000
#define DD   256
#define HH   8

#define LD_OP 1792   // [q | ka0 | ka1 | ka2 | va0 | va1 | va2]
#define LD_M  768    // [q | ka3 | va3]
#define OPB  2500    // op-aggregation blocks (8 warps each -> 20000 dst)
#define SCALE 0.17677669529663687f

// ---------------- scratch ----------------
__device__ float g_x0[N_OP * DD];
__device__ __nv_bfloat16 g_proj_op[(size_t)N_OP * LD_OP];
__device__ __nv_bfloat16 g_proj_m[N_M * LD_M];
__device__ float g_wop[LD_OP * DD];
__device__ float g_bop[LD_OP];
__device__ float g_wm[LD_M * DD];
__device__ float g_bm[LD_M];
__device__ float g_out_op[N_OP * DD];
__device__ float g_out_m[N_M * DD];
__device__ float g_tstat[300];               // [G 256 | a 16 | h 16 | c0 | c1]
__device__ float g_tacc[N_OP * 20];
// CSR: regions 0,1,2 = op-dst types (edge types 0,1,3); region 3 = machine-dst (type 2)
#define NCTR (3 * N_OP + N_M)
__device__ int g_cnt[NCTR];
__device__ int g_off[NCTR];
__device__ int g_cur[NCTR];
__device__ int g_elist[4 * NE];              // src ids, region t at t*NE (t = edge type)

struct GemmCfg {
    const float* A; const float* W; const float* bias; void* C;
    int M, lda, ldc, gx, gy;
    const float* skipX; int skipIdx; int outBF; int amode;  // amode 0=plain, 1=gelu-on-load
};

__device__ __forceinline__ void red_add_v4(float* p, float4 v) {
    asm volatile("red.global.add.v4.f32 [%0], {%1,%2,%3,%4};"
                 :: "l"(p), "f"(v.x), "f"(v.y), "f"(v.z), "f"(v.w) : "memory");
}

__device__ __forceinline__ unsigned f2tf32(float f) {
    unsigned u; asm("cvt.rna.tf32.f32 %0, %1;" : "=r"(u) : "f"(f)); return u;
}

__device__ __forceinline__ void mma_tf32(float* c, unsigned a0, unsigned a1,
                                         unsigned a2, unsigned a3,
                                         unsigned b0, unsigned b1) {
    asm volatile("mma.sync.aligned.m16n8k8.row.col.f32.tf32.tf32.f32 "
                 "{%0,%1,%2,%3}, {%4,%5,%6,%7}, {%8,%9}, {%0,%1,%2,%3};"
                 : "+f"(c[0]), "+f"(c[1]), "+f"(c[2]), "+f"(c[3])
                 : "r"(a0), "r"(a1), "r"(a2), "r"(a3), "r"(b0), "r"(b1));
}

__device__ __forceinline__ void bf8_to_f(const uint4 u, float* f) {
    float2 a = __bfloat1622float2(*(const __nv_bfloat162*)&u.x);
    float2 b = __bfloat1622float2(*(const __nv_bfloat162*)&u.y);
    float2 c = __bfloat1622float2(*(const __nv_bfloat162*)&u.z);
    float2 d = __bfloat1622float2(*(const __nv_bfloat162*)&u.w);
    f[0] = a.x; f[1] = a.y; f[2] = b.x; f[3] = b.y;
    f[4] = c.x; f[5] = c.y; f[6] = d.x; f[7] = d.y;
}

__device__ __forceinline__ float gelu1(float x) {
    return 0.5f * x * (1.f + erff(x * 0.70710678118654752f));
}

// ---------------- init + zero ----------------
__global__ void k_initzero(const float* __restrict__ x_op) {
    int i = blockIdx.x * blockDim.x + threadIdx.x;
    if (i < N_OP * DD / 4) ((float4*)g_x0)[i] = ((const float4*)x_op)[i];
    if (i < N_OP * 20 / 4) ((float4*)g_tacc)[i] = make_float4(0.f, 0.f, 0.f, 0.f);
    if (i < NCTR) g_cnt[i] = 0;
}

// ---------------- weight stacking ----------------
__global__ void k_wstack(const float* __restrict__ Wk, const float* __restrict__ bk,
                         const float* __restrict__ Wq, const float* __restrict__ bq,
                         const float* __restrict__ Wv, const float* __restrict__ bv,
                         const float* __restrict__ a_rel, const float* __restrict__ m_rel) {
    int row = blockIdx.x;
    int in = threadIdx.x;
    float* wdst; float* bdst; int t;
    if (row < LD_OP) { wdst = g_wop; bdst = g_bop; t = 0; }
    else             { row -= LD_OP; wdst = g_wm; bdst = g_bm; t = 1; }
    int seg = row >> 8, o = row & 255;
    if (seg == 0) {
        wdst[row * DD + in] = Wq[t * 65536 + o * DD + in];
        if (in == 0) bdst[row] = bq[t * DD + o];
        return;
    }
    const float* rel; const float* Wb; const float* bb; int e;
    if (t == 0) {
        if (seg <= 3) { e = seg - 1; rel = a_rel; Wb = Wk; bb = bk; }
        else          { e = seg - 4; rel = m_rel; Wb = Wv; bb = bv; }
    } else {
        e = 3;
        if (seg == 1) { rel = a_rel; Wb = Wk; bb = bk; }
        else          { rel = m_rel; Wb = Wv; bb = bv; }
    }
    int h = o >> 5, f = o & 31;
    const float* rp = rel + ((e * 8 + h) * 32) * 32 + f;
    const float* W = Wb + t * 65536 + (h * 32) * DD;
    float acc = 0.f;
#pragma unroll 8
    for (int d = 0; d < 32; d++) acc += rp[d * 32] * W[d * DD + in];
    wdst[row * DD + in] = acc;
    if (in == 0) {
        float bacc = 0.f;
        const float* b = bb + t * DD + h * 32;
        for (int d = 0; d < 32; d++) bacc += rp[d * 32] * b[d];
        bdst[row] = bacc;
    }
}

// ---------------- temporal stats precompute (fully warp-parallel) ----------------
__global__ void k_tprep(const float* __restrict__ Wt, const float* __restrict__ bt) {
    int b = blockIdx.x, t = threadIdx.x, w = t >> 5, lane = t & 31;
    if (b < 32) {                        // Gram entries, warp per entry
        int idx = b * 8 + w;
        int c = idx >> 4, d = idx & 15;
        float acc = 0.f;
        for (int i = lane; i < 256; i += 32) acc += Wt[i * 16 + c] * Wt[i * 16 + d];
#pragma unroll
        for (int o = 16; o; o >>= 1) acc += __shfl_xor_sync(0xffffffffu, acc, o);
        if (lane == 0) g_tstat[idx] = acc * (1.f / 256.f);
    } else if (b < 34) {                 // a[16], h[16], warp per entry
        int idx = (b - 32) * 8 + w;
        float a = 0.f, h = 0.f;
        for (int i = lane; i < 256; i += 32) {
            float wv = Wt[i * 16 + idx];
            a += wv; h += wv * bt[i];
        }
#pragma unroll
        for (int o = 16; o; o >>= 1) {
            a += __shfl_xor_sync(0xffffffffu, a, o);
            h += __shfl_xor_sync(0xffffffffu, h, o);
        }
        if (lane == 0) { g_tstat[256 + idx] = a * (1.f / 256.f); g_tstat[272 + idx] = h * (1.f / 256.f); }
    } else if (w == 0) {                 // c0, c1
        float c0 = 0.f, c1 = 0.f;
        for (int i = lane; i < 256; i += 32) { float v = bt[i]; c0 += v; c1 += v * v; }
#pragma unroll
        for (int o = 16; o; o >>= 1) {
            c0 += __shfl_xor_sync(0xffffffffu, c0, o);
            c1 += __shfl_xor_sync(0xffffffffu, c1, o);
        }
        if (lane == 0) { g_tstat[288] = c0 * (1.f / 256.f); g_tstat[289] = c1 * (1.f / 256.f); }
    }
}

// ---------------- temporal edge pass ----------------
__global__ void k_temporal2(const float* __restrict__ dtp, const int* __restrict__ ei, int E) {
    __shared__ float sG[256], sa[16], sh2[16], sc[2];
    int t = threadIdx.x;
    if (t < 256) sG[t] = g_tstat[t];
    if (t < 16) { sa[t] = g_tstat[256 + t]; sh2[t] = g_tstat[272 + t]; }
    if (t < 2) sc[t] = g_tstat[288 + t];
    __syncthreads();
    int e = blockIdx.x * blockDim.x + t;
    if (e >= E) return;
    float dt = dtp[e];
    float temb[16];
#pragma unroll
    for (int j = 0; j < 8; j++) {
        float s, c;
        sincosf(dt * exp2f(-1.2457230355827609f * (float)j), &s, &c);
        temb[2 * j] = s; temb[2 * j + 1] = c;
    }
    float mu = sc[0], hs = 0.f, q = 0.f;
#pragma unroll
    for (int c = 0; c < 16; c++) {
        mu += sa[c] * temb[c];
        hs += sh2[c] * temb[c];
        float r = 0.f;
#pragma unroll
        for (int d = 0; d < 16; d++) r += sG[c * 16 + d] * temb[d];
        q += r * temb[c];
    }
    float var = q + 2.f * hs + sc[1] - mu * mu;
    float rs = rsqrtf(var + 1e-5f);
    int src = ei[e];
    float* acc = g_tacc + (size_t)src * 20;
    red_add_v4(acc + 0,  make_float4(rs * temb[0],  rs * temb[1],  rs * temb[2],  rs * temb[3]));
    red_add_v4(acc + 4,  make_float4(rs * temb[4],  rs * temb[5],  rs * temb[6],  rs * temb[7]));
    red_add_v4(acc + 8,  make_float4(rs * temb[8],  rs * temb[9],  rs * temb[10], rs * temb[11]));
    red_add_v4(acc + 12, make_float4(rs * temb[12], rs * temb[13], rs * temb[14], rs * temb[15]));
    red_add_v4(acc + 16, make_float4(rs, rs * mu, 1.f, 0.f));
}

// ---------------- temporal finalize ----------------
__global__ void k_tfinal(const float* __restrict__ Wt, const float* __restrict__ bt,
                         const float* __restrict__ lng, const float* __restrict__ lnb) {
    __shared__ float s[20];
    int n = blockIdx.x, t = threadIdx.x;
    if (t < 20) s[t] = g_tacc[(size_t)n * 20 + t];
    __syncthreads();
    float cnt = s[18];
    if (cnt == 0.f) return;
    float sr = s[16], srm = s[17];
    const float4* wr = (const float4*)(Wt + t * 16);
    float4 w0 = wr[0], w1 = wr[1], w2 = wr[2], w3 = wr[3];
    float acc = w0.x * s[0] + w0.y * s[1] + w0.z * s[2] + w0.w * s[3]
              + w1.x * s[4] + w1.y * s[5] + w1.z * s[6] + w1.w * s[7]
              + w2.x * s[8] + w2.y * s[9] + w2.z * s[10] + w2.w * s[11]
              + w3.x * s[12] + w3.y * s[13] + w3.z * s[14] + w3.w * s[15];
    float y = lng[t] * (acc + sr * bt[t] - srm) + cnt * lnb[t];
    g_x0[(size_t)n * DD + t] += y;
}

// ---------------- CSR build: count / scan / scatter ----------------
__device__ __constant__ int c_rbase[4] = {0, N_OP, 3 * N_OP, 2 * N_OP};

__global__ void k_count(const int* e0, const int* e1, const int* e2, const int* e3,
                        int E0, int E1, int E2, int E3, int bpt) {
    int ty = blockIdx.x / bpt;
    const int* ei = (ty == 0) ? e0 : (ty == 1) ? e1 : (ty == 2) ? e2 : e3;
    int E = (ty == 0) ? E0 : (ty == 1) ? E1 : (ty == 2) ? E2 : E3;
    int idx = (blockIdx.x - ty * bpt) * 256 + threadIdx.x;
    if (idx >= E) return;
    atomicAdd(&g_cnt[c_rbase[ty] + ei[E + idx]], 1);
}

__global__ void k_scan() {      // 4 blocks x 1024
    __shared__ int sp[1024];
    int arr = blockIdx.x, t = threadIdx.x;
    int base = (arr < 3) ? arr * N_OP : 3 * N_OP;
    int len = (arr < 3) ? N_OP : N_M;
    int chunk = (len + 1023) / 1024;
    int s0 = t * chunk, s1 = min(s0 + chunk, len);
    int sum = 0;
    for (int i = s0; i < s1; i++) sum += g_cnt[base + i];
    sp[t] = sum;
    __syncthreads();
    for (int o = 1; o < 1024; o <<= 1) {
        int v = (t >= o) ? sp[t - o] : 0;
        __syncthreads();
        sp[t] += v;
        __syncthreads();
    }
    int run = (t > 0) ? sp[t - 1] : 0;
    for (int i = s0; i < s1; i++) {
        g_off[base + i] = run;
        g_cur[base + i] = run;
        run += g_cnt[base + i];
    }
}

__global__ void k_scatter(const int* e0, const int* e1, const int* e2, const int* e3,
                          int E0, int E1, int E2, int E3, int bpt) {
    int ty = blockIdx.x / bpt;
    const int* ei = (ty == 0) ? e0 : (ty == 1) ? e1 : (ty == 2) ? e2 : e3;
    int E = (ty == 0) ? E0 : (ty == 1) ? E1 : (ty == 2) ? E2 : E3;
    int idx = (blockIdx.x - ty * bpt) * 256 + threadIdx.x;
    if (idx >= E) return;
    int src = ei[idx], dst = ei[E + idx];
    int pos = atomicAdd(&g_cur[c_rbase[ty] + dst], 1);
    g_elist[ty * NE + pos] = src;
}

// ---------------- tf32 tensor-core GEMM, two configs per launch ----------------
__global__ void __launch_bounds__(256, 2)
k_gemm2(GemmCfg c0, GemmCfg c1, const float* __restrict__ skipP) {
    GemmCfg c = blockIdx.z ? c1 : c0;
    if (blockIdx.x >= (unsigned)c.gx || blockIdx.y >= (unsigned)c.gy) return;
    __shared__ unsigned sA[128][36];
    __shared__ unsigned sW[128][36];
    int tid = threadIdx.x;
    int lane = tid & 31, wid = tid >> 5;
    int gID = lane >> 2, tig = lane & 3;
    int mw = (wid >> 2) * 64, nw = (wid & 3) * 32;
    int m0 = blockIdx.y * 128, n0 = blockIdx.x * 128;
    int lr = tid >> 1;
    int lc0 = (tid & 1) * 16;
    float acc[4][4][4];
#pragma unroll
    for (int i = 0; i < 4; i++)
#pragma unroll
        for (int j = 0; j < 4; j++)
#pragma unroll
            for (int r = 0; r < 4; r++) acc[i][j][r] = 0.f;

    for (int k0 = 0; k0 < 256; k0 += 32) {
        int gm = m0 + lr;
#pragma unroll
        for (int j = 0; j < 4; j++) {
            int col = k0 + lc0 + j * 4;
            float4 v = make_float4(0.f, 0.f, 0.f, 0.f);
            if (gm < c.M) {
                v = *(const float4*)&c.A[(size_t)gm * c.lda + col];
                if (c.amode == 1) {
                    v.x = gelu1(v.x); v.y = gelu1(v.y);
                    v.z = gelu1(v.z); v.w = gelu1(v.w);
                }
            }
            sA[lr][lc0 + 4 * j + 0] = f2tf32(v.x);
            sA[lr][lc0 + 4 * j + 1] = f2tf32(v.y);
            sA[lr][lc0 + 4 * j + 2] = f2tf32(v.z);
            sA[lr][lc0 + 4 * j + 3] = f2tf32(v.w);
        }
#pragma unroll
        for (int j = 0; j < 4; j++) {
            float4 v = *(const float4*)&c.W[(size_t)(n0 + lr) * 256 + k0 + lc0 + j * 4];
            sW[lr][lc0 + 4 * j + 0] = f2tf32(v.x);
            sW[lr][lc0 + 4 * j + 1] = f2tf32(v.y);
            sW[lr][lc0 + 4 * j + 2] = f2tf32(v.z);
            sW[lr][lc0 + 4 * j + 3] = f2tf32(v.w);
        }
        __syncthreads();
#pragma unroll
        for (int kk = 0; kk < 32; kk += 8) {
            unsigned bfr[4][2];
#pragma unroll
            for (int nt = 0; nt < 4; nt++) {
                int n = nw + nt * 8 + gID;
                bfr[nt][0] = sW[n][kk + tig];
                bfr[nt][1] = sW[n][kk + tig + 4];
            }
#pragma unroll
            for (int mt = 0; mt < 4; mt++) {
                int m = mw + mt * 16 + gID;
                unsigned a0 = sA[m][kk + tig];
                unsigned a1 = sA[m + 8][kk + tig];
                unsigned a2 = sA[m][kk + tig + 4];
                unsigned a3 = sA[m + 8][kk + tig + 4];
#pragma unroll
                for (int nt = 0; nt < 4; nt++)
                    mma_tf32(acc[mt][nt], a0, a1, a2, a3, bfr[nt][0], bfr[nt][1]);
            }
        }
        __syncthreads();
    }

    bool hs = (c.skipX != nullptr);
    float sa = 0.f, sb2 = 0.f;
    if (hs) { float s = skipP[c.skipIdx]; sa = 1.f / (1.f + __expf(-s)); sb2 = 1.f - sa; }
#pragma unroll
    for (int mt = 0; mt < 4; mt++) {
#pragma unroll
        for (int half = 0; half < 2; half++) {
            int m = m0 + mw + mt * 16 + gID + half * 8;
            if (m < c.M) {
#pragma unroll
                for (int nt = 0; nt < 4; nt++) {
                    int n = n0 + nw + nt * 8 + tig * 2;
                    float v0 = acc[mt][nt][half * 2 + 0] + c.bias[n];
                    float v1 = acc[mt][nt][half * 2 + 1] + c.bias[n + 1];
                    if (hs) {
                        v0 = sa * v0 + sb2 * c.skipX[(size_t)m * DD + n];
                        v1 = sa * v1 + sb2 * c.skipX[(size_t)m * DD + n + 1];
                    }
                    if (c.outBF) {
                        __nv_bfloat162* cp = (__nv_bfloat162*)((__nv_bfloat16*)c.C + (size_t)m * c.ldc + n);
                        *cp = __floats2bfloat162_rn(v0, v1);
                    } else {
                        *(float2*)((float*)c.C + (size_t)m * c.ldc + n) = make_float2(v0, v1);
                    }
                }
            }
        }
    }
}

// ---------------- CSR aggregation: gather attention, no atomics ----------------
// blocks [0, OPB): warp per op dst.  blocks [OPB, OPB+N_M): block per machine dst.
__global__ void k_aggr(const float* __restrict__ prel) {
    __shared__ float sacc[8 * 256];
    __shared__ float sdn[64];
    int lane = threadIdx.x & 31, w = threadIdx.x >> 5;
    int head = lane >> 2;
    if (blockIdx.x < OPB) {
        int d = blockIdx.x * 8 + w;                 // < 20000
        const uint4* qrow = (const uint4*)(g_proj_op + (size_t)d * LD_OP);
        float qf[8]; bf8_to_f(qrow[lane], qf);
        float outv[8] = {0.f, 0.f, 0.f, 0.f, 0.f, 0.f, 0.f, 0.f};
#pragma unroll
        for (int tt = 0; tt < 3; tt++) {
            int type = (tt == 2) ? 3 : tt;
            const __nv_bfloat16 *kp, *vp; int ld;
            if (tt == 0)      { kp = g_proj_op + 256; vp = g_proj_op + 1024; ld = LD_OP; }
            else if (tt == 1) { kp = g_proj_op + 512; vp = g_proj_op + 1280; ld = LD_OP; }
            else              { kp = g_proj_m + 256;  vp = g_proj_m + 512;   ld = LD_M; }
            float pr = prel[type * 8 + head] * SCALE;
            int rb = tt * N_OP + d;
            int s = g_off[rb], n = g_cnt[rb];
            const int* lst = g_elist + type * NE + s;
            float acc[8] = {0.f, 0.f, 0.f, 0.f, 0.f, 0.f, 0.f, 0.f};
            float dn = 0.f;
            for (int i = 0; i < n; i++) {
                int src = lst[i];
                uint4 ku = *((const uint4*)(kp + (size_t)src * ld) + lane);
                uint4 vu = *((const uint4*)(vp + (size_t)src * ld) + lane);
                float kf[8], vf[8];
                bf8_to_f(ku, kf); bf8_to_f(vu, vf);
                float p = 0.f;
#pragma unroll
                for (int j = 0; j < 8; j++) p += qf[j] * kf[j];
                p += __shfl_xor_sync(0xffffffffu, p, 1);
                p += __shfl_xor_sync(0xffffffffu, p, 2);
                float ex = __expf(p * pr);
                dn += ex;
#pragma unroll
                for (int j = 0; j < 8; j++) acc[j] += vf[j] * ex;
            }
            if (dn > 0.f) {
                float inv = 1.f / dn;
#pragma unroll
                for (int j = 0; j < 8; j++) outv[j] += acc[j] * inv;
            }
        }
        float* o = &g_out_op[(size_t)d * DD + lane * 8];
        *(float4*)o = make_float4(outv[0], outv[1], outv[2], outv[3]);
        *(float4*)(o + 4) = make_float4(outv[4], outv[5], outv[6], outv[7]);
    } else {
        int d = blockIdx.x - OPB;                   // machine dst
        const uint4* qrow = (const uint4*)(g_proj_m + (size_t)d * LD_M);
        float qf[8]; bf8_to_f(qrow[lane], qf);
        float pr = prel[16 + head] * SCALE;
        int rb = 3 * N_OP + d;
        int s = g_off[rb], n = g_cnt[rb];
        const int* lst = g_elist + 2 * NE + s;
        float acc[8] = {0.f, 0.f, 0.f, 0.f, 0.f, 0.f, 0.f, 0.f};
        float dn = 0.f;
        for (int i = w; i < n; i += 8) {
            int src = lst[i];
            uint4 ku = *((const uint4*)(g_proj_op + (size_t)src * LD_OP + 768) + lane);
            uint4 vu = *((const uint4*)(g_proj_op + (size_t)src * LD_OP + 1536) + lane);
            float kf[8], vf[8];
            bf8_to_f(ku, kf); bf8_to_f(vu, vf);
            float p = 0.f;
#pragma unroll
            for (int j = 0; j < 8; j++) p += qf[j] * kf[j];
            p += __shfl_xor_sync(0xffffffffu, p, 1);
            p += __shfl_xor_sync(0xffffffffu, p, 2);
            float ex = __expf(p * pr);
            dn += ex;
#pragma unroll
            for (int j = 0; j < 8; j++) acc[j] += vf[j] * ex;
        }
#pragma unroll
        for (int j = 0; j < 8; j++) sacc[w * 256 + lane * 8 + j] = acc[j];
        if ((lane & 3) == 0) sdn[w * 8 + head] = dn;
        __syncthreads();
        int ch = threadIdx.x, hd = ch >> 5;
        float sv = 0.f, Dv = 0.f;
#pragma unroll
        for (int w2 = 0; w2 < 8; w2++) {
            sv += sacc[w2 * 256 + ch];
            Dv += sdn[w2 * 8 + hd];
        }
        g_out_m[(size_t)d * DD + ch] = (Dv > 0.f) ? sv / Dv : 0.f;
    }
}

// ---------------- launch ----------------
extern "C" void kernel_launch(void* const* d_in, const int* in_sizes, int n_in,
                              void* d_out, int out_size) {
    const float* x_op = (const float*)d_in[0];
    const float* x_m  = (const float*)d_in[1];
    const float* dtp  = (const float*)d_in[2];
    const int* ei_mp  = (const int*)d_in[3];
    const int* ei_pr  = (const int*)d_in[4];
    const int* ei_on  = (const int*)d_in[5];
    const int* ei_ho  = (const int*)d_in[6];
    const float* Wt   = (const float*)d_in[7];
    const float* bt   = (const float*)d_in[8];
    const float* lng  = (const float*)d_in[9];
    const float* lnb  = (const float*)d_in[10];
    const float* Wk   = (const float*)d_in[11];
    const float* bk   = (const float*)d_in[12];
    const float* Wq   = (const float*)d_in[13];
    const float* bq   = (const float*)d_in[14];
    const float* Wv   = (const float*)d_in[15];
    const float* bv   = (const float*)d_in[16];
    const float* Wa   = (const float*)d_in[17];
    const float* ba   = (const float*)d_in[18];
    const float* skip = (const float*)d_in[19];
    const float* a_rel = (const float*)d_in[20];
    const float* m_rel = (const float*)d_in[21];
    const float* p_rel = (const float*)d_in[22];
    float* out = (float*)d_out;

    float *p_x0, *p_wop, *p_bop, *p_wm, *p_bm, *p_oop, *p_om;
    __nv_bfloat16 *p_pop, *p_pm;
    cudaGetSymbolAddress((void**)&p_x0, g_x0);
    cudaGetSymbolAddress((void**)&p_pop, g_proj_op);
    cudaGetSymbolAddress((void**)&p_pm, g_proj_m);
    cudaGetSymbolAddress((void**)&p_wop, g_wop);
    cudaGetSymbolAddress((void**)&p_bop, g_bop);
    cudaGetSymbolAddress((void**)&p_wm, g_wm);
    cudaGetSymbolAddress((void**)&p_bm, g_bm);
    cudaGetSymbolAddress((void**)&p_oop, g_out_op);
    cudaGetSymbolAddress((void**)&p_om, g_out_m);

    int E0 = in_sizes[3] / 2, E1 = in_sizes[4] / 2, E2 = in_sizes[5] / 2, E3 = in_sizes[6] / 2;

    k_initzero<<<(N_OP * DD / 4 + 255) / 256, 256>>>(x_op);
    k_wstack<<<LD_OP + LD_M, 256>>>(Wk, bk, Wq, bq, Wv, bv, a_rel, m_rel);
    k_tprep<<<35, 256>>>(Wt, bt);
    k_temporal2<<<(E0 + 255) / 256, 256>>>(dtp, ei_mp, E0);
    k_tfinal<<<N_OP, 256>>>(Wt, bt, lng, lnb);

    // CSR build
    int Emax = E0;
    if (E1 > Emax) Emax = E1;
    if (E2 > Emax) Emax = E2;
    if (E3 > Emax) Emax = E3;
    int bpt = (Emax + 255) / 256;
    k_count<<<4 * bpt, 256>>>(ei_mp, ei_pr, ei_on, ei_ho, E0, E1, E2, E3, bpt);
    k_scan<<<4, 1024>>>();
    k_scatter<<<4 * bpt, 256>>>(ei_mp, ei_pr, ei_on, ei_ho, E0, E1, E2, E3, bpt);

    // stacked projections (op + machine in one launch, bf16 out)
    {
        GemmCfg cOp = {p_x0, p_wop, p_bop, p_pop, N_OP, DD, LD_OP,
                       LD_OP / 128, (N_OP + 127) / 128, nullptr, 0, 1, 0};
        GemmCfg cM  = {x_m, p_wm, p_bm, p_pm, N_M, DD, LD_M,
                       LD_M / 128, (N_M + 127) / 128, nullptr, 0, 1, 0};
        k_gemm2<<<dim3(LD_OP / 128, (N_OP + 127) / 128, 2), 256>>>(cOp, cM, nullptr);
    }

    // CSR gather aggregation (no atomics)
    k_aggr<<<OPB + N_M, 256>>>(p_rel);

    // final GEMMs: GELU-on-load + sigmoid-gated skip, fp32 to d_out
    {
        GemmCfg cOp = {p_oop, Wa, ba, out, N_OP, DD, DD,
                       2, (N_OP + 127) / 128, p_x0, 0, 0, 1};
        GemmCfg cM  = {p_om, Wa + 65536, ba + 256, out + (size_t)N_OP * DD, N_M, DD, DD,
                       2, (N_M + 127) / 128, x_m, 1, 0, 1};
        k_gemm2<<<dim3(2, (N_OP + 127) / 128, 2), 256>>>(cOp, cM, skip);
    }
}